// round 1
// baseline (speedup 1.0000x reference)
#include <cuda_runtime.h>
#include <cuda_bf16.h>
#include <math.h>

// Problem constants (B=2, T=2048, C=1024, H=16, D=64)
#define BATCH 2
#define SEQ   2048
#define CDIM  1024
#define NHEAD 16
#define HDIM  64
#define MROWS (BATCH*SEQ)          // 4096

// Scratch (device globals: the sanctioned alloc-free scratch path)
__device__ float g_qkv[(size_t)MROWS * 3 * CDIM];   // [4096, 3072]
__device__ float g_att[(size_t)MROWS * CDIM];       // [4096, 1024]

// ---------------------------------------------------------------------------
// SGEMM: C[M,N] = A[M,K] @ B[K,N] (+ bias). 128x128x16 tile, 256 threads,
// 8x8 per thread with split-quad layout (conflict-free LDS.128).
// ---------------------------------------------------------------------------
template<int Mv, int Nv, int Kv, bool BIAS>
__global__ __launch_bounds__(256) void sgemm_kernel(
    const float* __restrict__ A, const float* __restrict__ Bm,
    const float* __restrict__ bias, float* __restrict__ C)
{
    constexpr int BK = 16;
    __shared__ float As[BK][136];   // padded; stored transposed
    __shared__ float Bs[BK][128];

    const int tid = threadIdx.x;
    const int bm = blockIdx.y * 128;
    const int bn = blockIdx.x * 128;
    const int tx = tid & 15;        // col group
    const int ty = tid >> 4;        // row group

    const int aRow = tid >> 2;          // 0..63
    const int aCol = (tid & 3) << 2;    // 0,4,8,12
    const int bRow = tid >> 5;          // 0..7
    const int bCol = (tid & 31) << 2;   // 0..124

    const float* Aptr = A + (size_t)(bm + aRow) * Kv + aCol;
    const float* Bptr = Bm + (size_t)bRow * Nv + bn + bCol;

    float acc[8][8];
    #pragma unroll
    for (int i = 0; i < 8; i++)
        #pragma unroll
        for (int j = 0; j < 8; j++) acc[i][j] = 0.f;

    for (int k0 = 0; k0 < Kv; k0 += BK) {
        float4 a0 = *(const float4*)(Aptr);
        float4 a1 = *(const float4*)(Aptr + (size_t)64 * Kv);
        float4 b0 = *(const float4*)(Bptr);
        float4 b1 = *(const float4*)(Bptr + (size_t)8 * Nv);
        __syncthreads();
        As[aCol + 0][aRow]      = a0.x;
        As[aCol + 1][aRow]      = a0.y;
        As[aCol + 2][aRow]      = a0.z;
        As[aCol + 3][aRow]      = a0.w;
        As[aCol + 0][aRow + 64] = a1.x;
        As[aCol + 1][aRow + 64] = a1.y;
        As[aCol + 2][aRow + 64] = a1.z;
        As[aCol + 3][aRow + 64] = a1.w;
        *(float4*)&Bs[bRow][bCol]     = b0;
        *(float4*)&Bs[bRow + 8][bCol] = b1;
        __syncthreads();

        #pragma unroll
        for (int kk = 0; kk < BK; ++kk) {
            float4 av0 = *(const float4*)&As[kk][ty * 4];
            float4 av1 = *(const float4*)&As[kk][64 + ty * 4];
            float4 bv0 = *(const float4*)&Bs[kk][tx * 4];
            float4 bv1 = *(const float4*)&Bs[kk][64 + tx * 4];
            float ar[8] = {av0.x, av0.y, av0.z, av0.w, av1.x, av1.y, av1.z, av1.w};
            float br[8] = {bv0.x, bv0.y, bv0.z, bv0.w, bv1.x, bv1.y, bv1.z, bv1.w};
            #pragma unroll
            for (int i = 0; i < 8; i++)
                #pragma unroll
                for (int j = 0; j < 8; j++)
                    acc[i][j] = fmaf(ar[i], br[j], acc[i][j]);
        }
        Aptr += BK;
        Bptr += (size_t)BK * Nv;
    }

    const int c0 = bn + tx * 4;
    const int c1 = bn + 64 + tx * 4;
    float4 bias0 = make_float4(0.f, 0.f, 0.f, 0.f);
    float4 bias1 = make_float4(0.f, 0.f, 0.f, 0.f);
    if (BIAS) {
        bias0 = *(const float4*)(bias + c0);
        bias1 = *(const float4*)(bias + c1);
    }
    #pragma unroll
    for (int i = 0; i < 8; i++) {
        int row = bm + ((i < 4) ? (ty * 4 + i) : (64 + ty * 4 + i - 4));
        float4 o0 = make_float4(acc[i][0] + bias0.x, acc[i][1] + bias0.y,
                                acc[i][2] + bias0.z, acc[i][3] + bias0.w);
        float4 o1 = make_float4(acc[i][4] + bias1.x, acc[i][5] + bias1.y,
                                acc[i][6] + bias1.z, acc[i][7] + bias1.w);
        *(float4*)&C[(size_t)row * Nv + c0] = o0;
        *(float4*)&C[(size_t)row * Nv + c1] = o1;
    }
}

// ---------------------------------------------------------------------------
// Flash attention (fp32, causal, online softmax).
// Grid: (T/64, B*H). 128 threads; 2 threads per q-row (paired via shfl).
// Q row in registers; K/V/S tiles in smem (stride 68 floats).
// ---------------------------------------------------------------------------
#define STRD 68
__global__ __launch_bounds__(128) void flash_kernel(
    const float* __restrict__ qkv, float* __restrict__ att)
{
    extern __shared__ float sm[];
    float* Qs = sm;
    float* Ks = Qs + 64 * STRD;
    float* Vs = Ks + 64 * STRD;
    float* Ss = Vs + 64 * STRD;

    const int t = threadIdx.x;       // 0..127
    const int r = t >> 1;            // q row in tile
    const int p = t & 1;             // half / parity
    const int qtile = blockIdx.x;
    const int bh = blockIdx.y;
    const int b = bh >> 4;
    const int h = bh & 15;

    const size_t rowstride = 3 * CDIM;
    const float* qb = qkv + (size_t)b * SEQ * rowstride + h * HDIM;
    const float* kb = qb + CDIM;
    const float* vb = qb + 2 * CDIM;
    const int qbase = qtile * 64;

    // Load Q tile -> smem, then own row -> registers
    {
        const float4* src = (const float4*)(qb + (size_t)(qbase + r) * rowstride + p * 32);
        float4* dst = (float4*)(Qs + r * STRD + p * 32);
        #pragma unroll
        for (int i = 0; i < 8; i++) dst[i] = src[i];
    }
    __syncthreads();
    float4 q4[16];
    {
        const float4* qrow = (const float4*)(Qs + r * STRD);
        #pragma unroll
        for (int i = 0; i < 16; i++) q4[i] = qrow[i];
    }

    float m = -INFINITY, l = 0.f;
    float4 o4[8];
    #pragma unroll
    for (int j = 0; j < 8; j++) o4[j] = make_float4(0.f, 0.f, 0.f, 0.f);
    const float scale = 0.125f;   // 1/sqrt(64)

    for (int kt = 0; kt <= qtile; ++kt) {
        __syncthreads();   // previous PV done before reloading K/V
        {
            const float4* ks = (const float4*)(kb + (size_t)(kt * 64 + r) * rowstride + p * 32);
            float4* kd = (float4*)(Ks + r * STRD + p * 32);
            #pragma unroll
            for (int i = 0; i < 8; i++) kd[i] = ks[i];
            const float4* vsrc = (const float4*)(vb + (size_t)(kt * 64 + r) * rowstride + p * 32);
            float4* vd = (float4*)(Vs + r * STRD + p * 32);
            #pragma unroll
            for (int i = 0; i < 8; i++) vd[i] = vsrc[i];
        }
        __syncthreads();

        // S = Q K^T * scale (+ causal mask on diagonal tile)
        const bool diag = (kt == qtile);
        for (int cc = 0; cc < 32; ++cc) {
            const int c = 2 * cc + p;
            const float4* krow = (const float4*)(Ks + c * STRD);
            float accv = 0.f;
            #pragma unroll
            for (int i = 0; i < 16; i++) {
                float4 kv = krow[i];
                accv = fmaf(q4[i].x, kv.x, accv);
                accv = fmaf(q4[i].y, kv.y, accv);
                accv = fmaf(q4[i].z, kv.z, accv);
                accv = fmaf(q4[i].w, kv.w, accv);
            }
            float s = accv * scale;
            if (diag && (kt * 64 + c) > (qbase + r)) s = -INFINITY;
            Ss[r * STRD + c] = s;
        }
        __syncthreads();

        // Online softmax (pair merged via shfl_xor lane^1)
        float rmax = -INFINITY;
        for (int cc = 0; cc < 32; ++cc)
            rmax = fmaxf(rmax, Ss[r * STRD + 2 * cc + p]);
        rmax = fmaxf(rmax, __shfl_xor_sync(0xffffffffu, rmax, 1));
        const float mnew = fmaxf(m, rmax);
        const float corr = __expf(m - mnew);
        float ps = 0.f;
        for (int cc = 0; cc < 32; ++cc) {
            const int c = 2 * cc + p;
            const float e = __expf(Ss[r * STRD + c] - mnew);
            Ss[r * STRD + c] = e;
            ps += e;
        }
        ps += __shfl_xor_sync(0xffffffffu, ps, 1);
        l = l * corr + ps;
        m = mnew;
        #pragma unroll
        for (int j = 0; j < 8; j++) {
            o4[j].x *= corr; o4[j].y *= corr; o4[j].z *= corr; o4[j].w *= corr;
        }
        __syncthreads();

        // O += P @ V   (thread owns interleaved float4 columns: dc4 = p + 2*j)
        for (int c = 0; c < 64; ++c) {
            const float pp = Ss[r * STRD + c];
            const float4* vrow = (const float4*)(Vs + c * STRD);
            #pragma unroll
            for (int j = 0; j < 8; j++) {
                float4 vv = vrow[p + 2 * j];
                o4[j].x = fmaf(pp, vv.x, o4[j].x);
                o4[j].y = fmaf(pp, vv.y, o4[j].y);
                o4[j].z = fmaf(pp, vv.z, o4[j].z);
                o4[j].w = fmaf(pp, vv.w, o4[j].w);
            }
        }
    }

    const float inv = 1.f / l;
    float* out = att + (size_t)(b * SEQ + qbase + r) * CDIM + h * HDIM;
    #pragma unroll
    for (int j = 0; j < 8; j++) {
        float4 v = make_float4(o4[j].x * inv, o4[j].y * inv, o4[j].z * inv, o4[j].w * inv);
        ((float4*)out)[p + 2 * j] = v;
    }
}

// ---------------------------------------------------------------------------
extern "C" void kernel_launch(void* const* d_in, const int* in_sizes, int n_in,
                              void* d_out, int out_size)
{
    const float* x      = (const float*)d_in[0];   // [B,T,C]
    const float* w_qkv  = (const float*)d_in[1];   // [C,3C]
    const float* w_proj = (const float*)d_in[2];   // [C,C]
    const float* b_proj = (const float*)d_in[3];   // [C]
    float* out = (float*)d_out;

    float* qkvp; float* attp;
    cudaGetSymbolAddress((void**)&qkvp, g_qkv);
    cudaGetSymbolAddress((void**)&attp, g_att);

    // 1) QKV projection: [4096,1024] @ [1024,3072]
    sgemm_kernel<MROWS, 3 * CDIM, CDIM, false>
        <<<dim3((3 * CDIM) / 128, MROWS / 128), 256>>>(x, w_qkv, nullptr, qkvp);

    // 2) Causal flash attention
    const size_t shm = 4 * 64 * STRD * sizeof(float);   // ~68 KB
    cudaFuncSetAttribute(flash_kernel, cudaFuncAttributeMaxDynamicSharedMemorySize, (int)shm);
    flash_kernel<<<dim3(SEQ / 64, BATCH * NHEAD), 128, shm>>>(qkvp, attp);

    // 3) Output projection + bias: [4096,1024] @ [1024,1024]
    sgemm_kernel<MROWS, CDIM, CDIM, true>
        <<<dim3(CDIM / 128, MROWS / 128), 256>>>(attp, w_proj, b_proj, out);
}

// round 3
// speedup vs baseline: 1.3558x; 1.3558x over previous
#include <cuda_runtime.h>
#include <cuda_bf16.h>
#include <math.h>
#include <stdint.h>

// Problem constants (B=2, T=2048, C=1024, H=16, D=64)
#define BATCH 2
#define SEQ   2048
#define CDIM  1024
#define NHEAD 16
#define HDIM  64
#define MROWS (BATCH*SEQ)          // 4096
#define KDIM  CDIM

// Scratch (device globals: sanctioned alloc-free scratch)
__device__ float g_qkv[(size_t)MROWS * 3 * CDIM];     // [4096, 3072]
__device__ float g_att[(size_t)MROWS * CDIM];         // [4096, 1024]
__device__ float g_wqkvT[(size_t)3 * CDIM * CDIM];    // [3072, 1024]
__device__ float g_wprojT[(size_t)CDIM * CDIM];       // [1024, 1024]

// ---------------------------------------------------------------------------
// helpers
// ---------------------------------------------------------------------------
__device__ __forceinline__ uint32_t smem_to_u32(const void* p) {
    uint32_t a;
    asm("{ .reg .u64 t; cvta.to.shared.u64 t, %1; cvt.u32.u64 %0, t; }" : "=r"(a) : "l"(p));
    return a;
}
__device__ __forceinline__ uint32_t tf32r(float v) {
    uint32_t r;
    asm("cvt.rna.tf32.f32 %0, %1;" : "=r"(r) : "f"(v));
    return r;
}
#define CP_ASYNC16(dst, src) \
    asm volatile("cp.async.cg.shared.global [%0], [%1], 16;" :: "r"(dst), "l"(src))
#define CP_COMMIT() asm volatile("cp.async.commit_group;" ::: "memory")
#define CP_WAIT(n)  asm volatile("cp.async.wait_group %0;" :: "n"(n) : "memory")

__device__ __forceinline__ void mma_tf32(float* c, const uint32_t* a, const uint32_t* b) {
    asm volatile(
        "mma.sync.aligned.m16n8k8.row.col.f32.tf32.tf32.f32 "
        "{%0,%1,%2,%3}, {%4,%5,%6,%7}, {%8,%9}, {%0,%1,%2,%3};"
        : "+f"(c[0]), "+f"(c[1]), "+f"(c[2]), "+f"(c[3])
        : "r"(a[0]), "r"(a[1]), "r"(a[2]), "r"(a[3]), "r"(b[0]), "r"(b[1]));
}

// ===========================================================================
// tf32 mma.sync GEMM: C[M,Nn] = A[M,1024] @ BT[Nn,1024]^T (+bias)
// CTA tile 128x128, K-chunk 32, 8 warps (warp tile 32x64),
// cp.async double-buffered smem, stride-36 padding (conflict-free frags).
// ===========================================================================
#define TSTR 36                      // smem row stride in floats (144B, 16B-aligned)
#define TILE_F (128 * TSTR)          // floats per tile buffer
#define GEMM_SMEM (4 * TILE_F * 4)   // 73728 bytes

template<int Nn, bool BIAS>
__global__ __launch_bounds__(256) void gemm_mma(
    const float* __restrict__ A, const float* __restrict__ BT,
    const float* __restrict__ bias, float* __restrict__ C)
{
    extern __shared__ __align__(16) float smf[];
    float* sA[2] = { smf,              smf + 2 * TILE_F };
    float* sB[2] = { smf + TILE_F,     smf + 3 * TILE_F };
    const uint32_t sAu[2] = { smem_to_u32(sA[0]), smem_to_u32(sA[1]) };
    const uint32_t sBu[2] = { smem_to_u32(sB[0]), smem_to_u32(sB[1]) };

    const int tid = threadIdx.x, lane = tid & 31, wid = tid >> 5;
    const int m0 = blockIdx.y * 128, n0 = blockIdx.x * 128;
    const int mw = (wid & 3) * 32;   // warp m offset
    const int nw = (wid >> 2) * 64;  // warp n offset
    const int g = lane >> 2, t4 = lane & 3;

    const float* Ab = A + (size_t)m0 * KDIM;
    const float* Bb = BT + (size_t)n0 * KDIM;

    // prefetch one 128x32 chunk of A and BT into buffer s
    auto prefetch = [&](int kc, int s) {
        const int kb = kc * 32;
        #pragma unroll
        for (int q = 0; q < 4; q++) {
            const int f = tid + q * 256;
            const int row = f >> 3, c4 = f & 7;
            CP_ASYNC16(sAu[s] + row * (TSTR * 4) + c4 * 16,
                       Ab + (size_t)row * KDIM + kb + c4 * 4);
            CP_ASYNC16(sBu[s] + row * (TSTR * 4) + c4 * 16,
                       Bb + (size_t)row * KDIM + kb + c4 * 4);
        }
        CP_COMMIT();
    };

    float acc[2][8][4];
    #pragma unroll
    for (int i = 0; i < 2; i++)
        #pragma unroll
        for (int j = 0; j < 8; j++)
            #pragma unroll
            for (int q = 0; q < 4; q++) acc[i][j][q] = 0.f;

    prefetch(0, 0);
    prefetch(1, 1);

    for (int kc = 0; kc < 32; ++kc) {
        const int s = kc & 1;
        if (kc < 31) { CP_WAIT(1); } else { CP_WAIT(0); }
        __syncthreads();

        const float* __restrict__ As = sA[s];
        const float* __restrict__ Bs = sB[s];
        #pragma unroll
        for (int ks = 0; ks < 4; ++ks) {
            const int kb = ks * 8;
            uint32_t a[2][4], b[8][2];
            #pragma unroll
            for (int i = 0; i < 2; i++) {
                a[i][0] = tf32r(As[(mw + 16 * i + g) * TSTR + kb + t4]);
                a[i][1] = tf32r(As[(mw + 16 * i + g + 8) * TSTR + kb + t4]);
                a[i][2] = tf32r(As[(mw + 16 * i + g) * TSTR + kb + t4 + 4]);
                a[i][3] = tf32r(As[(mw + 16 * i + g + 8) * TSTR + kb + t4 + 4]);
            }
            #pragma unroll
            for (int j = 0; j < 8; j++) {
                b[j][0] = __float_as_uint(Bs[(nw + 8 * j + g) * TSTR + kb + t4]);
                b[j][1] = __float_as_uint(Bs[(nw + 8 * j + g) * TSTR + kb + t4 + 4]);
            }
            #pragma unroll
            for (int i = 0; i < 2; i++)
                #pragma unroll
                for (int j = 0; j < 8; j++)
                    mma_tf32(acc[i][j], a[i], b[j]);
        }
        __syncthreads();
        if (kc + 2 < 32) prefetch(kc + 2, s);
    }

    // epilogue: direct global stores (float2 per c-pair)
    #pragma unroll
    for (int i = 0; i < 2; i++) {
        const int r0 = m0 + mw + 16 * i + g;
        const int r1 = r0 + 8;
        #pragma unroll
        for (int j = 0; j < 8; j++) {
            const int col = n0 + nw + 8 * j + 2 * t4;
            float2 bv = make_float2(0.f, 0.f);
            if (BIAS) bv = *(const float2*)(bias + col);
            *(float2*)(C + (size_t)r0 * Nn + col) =
                make_float2(acc[i][j][0] + bv.x, acc[i][j][1] + bv.y);
            *(float2*)(C + (size_t)r1 * Nn + col) =
                make_float2(acc[i][j][2] + bv.x, acc[i][j][3] + bv.y);
        }
    }
}

// ===========================================================================
// Transpose with tf32 rounding: in [R, Cc] -> out [Cc, R]
// ===========================================================================
__global__ __launch_bounds__(256) void transpose_tf32(
    const float* __restrict__ in, float* __restrict__ out, int R, int Cc)
{
    __shared__ float tile[32][33];
    const int x = blockIdx.x * 32 + threadIdx.x;
    const int y0 = blockIdx.y * 32;
    #pragma unroll
    for (int j = threadIdx.y; j < 32; j += 8)
        tile[j][threadIdx.x] = in[(size_t)(y0 + j) * Cc + x];
    __syncthreads();
    const int x2 = y0 + threadIdx.x;
    const int y2 = blockIdx.x * 32;
    #pragma unroll
    for (int j = threadIdx.y; j < 32; j += 8)
        ((uint32_t*)out)[(size_t)(y2 + j) * R + x2] = tf32r(tile[threadIdx.x][j]);
}

// ===========================================================================
// Flash attention (fp32, causal, online softmax) — unchanged (R1-passing)
// ===========================================================================
#define STRD 68
__global__ __launch_bounds__(128) void flash_kernel(
    const float* __restrict__ qkv, float* __restrict__ att)
{
    extern __shared__ float sm[];
    float* Qs = sm;
    float* Ks = Qs + 64 * STRD;
    float* Vs = Ks + 64 * STRD;
    float* Ss = Vs + 64 * STRD;

    const int t = threadIdx.x;
    const int r = t >> 1;
    const int p = t & 1;
    const int qtile = blockIdx.x;
    const int bh = blockIdx.y;
    const int b = bh >> 4;
    const int h = bh & 15;

    const size_t rowstride = 3 * CDIM;
    const float* qb = qkv + (size_t)b * SEQ * rowstride + h * HDIM;
    const float* kb = qb + CDIM;
    const float* vb = qb + 2 * CDIM;
    const int qbase = qtile * 64;

    {
        const float4* src = (const float4*)(qb + (size_t)(qbase + r) * rowstride + p * 32);
        float4* dst = (float4*)(Qs + r * STRD + p * 32);
        #pragma unroll
        for (int i = 0; i < 8; i++) dst[i] = src[i];
    }
    __syncthreads();
    float4 q4[16];
    {
        const float4* qrow = (const float4*)(Qs + r * STRD);
        #pragma unroll
        for (int i = 0; i < 16; i++) q4[i] = qrow[i];
    }

    float m = -INFINITY, l = 0.f;
    float4 o4[8];
    #pragma unroll
    for (int j = 0; j < 8; j++) o4[j] = make_float4(0.f, 0.f, 0.f, 0.f);
    const float scale = 0.125f;

    for (int kt = 0; kt <= qtile; ++kt) {
        __syncthreads();
        {
            const float4* ks = (const float4*)(kb + (size_t)(kt * 64 + r) * rowstride + p * 32);
            float4* kd = (float4*)(Ks + r * STRD + p * 32);
            #pragma unroll
            for (int i = 0; i < 8; i++) kd[i] = ks[i];
            const float4* vsrc = (const float4*)(vb + (size_t)(kt * 64 + r) * rowstride + p * 32);
            float4* vd = (float4*)(Vs + r * STRD + p * 32);
            #pragma unroll
            for (int i = 0; i < 8; i++) vd[i] = vsrc[i];
        }
        __syncthreads();

        const bool diag = (kt == qtile);
        for (int cc = 0; cc < 32; ++cc) {
            const int c = 2 * cc + p;
            const float4* krow = (const float4*)(Ks + c * STRD);
            float accv = 0.f;
            #pragma unroll
            for (int i = 0; i < 16; i++) {
                float4 kv = krow[i];
                accv = fmaf(q4[i].x, kv.x, accv);
                accv = fmaf(q4[i].y, kv.y, accv);
                accv = fmaf(q4[i].z, kv.z, accv);
                accv = fmaf(q4[i].w, kv.w, accv);
            }
            float s = accv * scale;
            if (diag && (kt * 64 + c) > (qbase + r)) s = -INFINITY;
            Ss[r * STRD + c] = s;
        }
        __syncthreads();

        float rmax = -INFINITY;
        for (int cc = 0; cc < 32; ++cc)
            rmax = fmaxf(rmax, Ss[r * STRD + 2 * cc + p]);
        rmax = fmaxf(rmax, __shfl_xor_sync(0xffffffffu, rmax, 1));
        const float mnew = fmaxf(m, rmax);
        const float corr = __expf(m - mnew);
        float ps = 0.f;
        for (int cc = 0; cc < 32; ++cc) {
            const int c = 2 * cc + p;
            const float e = __expf(Ss[r * STRD + c] - mnew);
            Ss[r * STRD + c] = e;
            ps += e;
        }
        ps += __shfl_xor_sync(0xffffffffu, ps, 1);
        l = l * corr + ps;
        m = mnew;
        #pragma unroll
        for (int j = 0; j < 8; j++) {
            o4[j].x *= corr; o4[j].y *= corr; o4[j].z *= corr; o4[j].w *= corr;
        }
        __syncthreads();

        for (int c = 0; c < 64; ++c) {
            const float pp = Ss[r * STRD + c];
            const float4* vrow = (const float4*)(Vs + c * STRD);
            #pragma unroll
            for (int j = 0; j < 8; j++) {
                float4 vv = vrow[p + 2 * j];
                o4[j].x = fmaf(pp, vv.x, o4[j].x);
                o4[j].y = fmaf(pp, vv.y, o4[j].y);
                o4[j].z = fmaf(pp, vv.z, o4[j].z);
                o4[j].w = fmaf(pp, vv.w, o4[j].w);
            }
        }
    }

    const float inv = 1.f / l;
    float* out = att + (size_t)(b * SEQ + qbase + r) * CDIM + h * HDIM;
    #pragma unroll
    for (int j = 0; j < 8; j++) {
        float4 v = make_float4(o4[j].x * inv, o4[j].y * inv, o4[j].z * inv, o4[j].w * inv);
        ((float4*)out)[p + 2 * j] = v;
    }
}

// ===========================================================================
extern "C" void kernel_launch(void* const* d_in, const int* in_sizes, int n_in,
                              void* d_out, int out_size)
{
    const float* x      = (const float*)d_in[0];
    const float* w_qkv  = (const float*)d_in[1];
    const float* w_proj = (const float*)d_in[2];
    const float* b_proj = (const float*)d_in[3];
    float* out = (float*)d_out;

    float *qkvp, *attp, *wqkvT, *wprojT;
    cudaGetSymbolAddress((void**)&qkvp, g_qkv);
    cudaGetSymbolAddress((void**)&attp, g_att);
    cudaGetSymbolAddress((void**)&wqkvT, g_wqkvT);
    cudaGetSymbolAddress((void**)&wprojT, g_wprojT);

    cudaFuncSetAttribute(gemm_mma<3 * CDIM, false>,
                         cudaFuncAttributeMaxDynamicSharedMemorySize, GEMM_SMEM);
    cudaFuncSetAttribute(gemm_mma<CDIM, true>,
                         cudaFuncAttributeMaxDynamicSharedMemorySize, GEMM_SMEM);

    // 0) Pre-transpose + tf32-round weights
    transpose_tf32<<<dim3(3 * CDIM / 32, CDIM / 32), dim3(32, 8)>>>(w_qkv, wqkvT, CDIM, 3 * CDIM);
    transpose_tf32<<<dim3(CDIM / 32, CDIM / 32), dim3(32, 8)>>>(w_proj, wprojT, CDIM, CDIM);

    // 1) QKV projection via mma.sync tf32
    gemm_mma<3 * CDIM, false>
        <<<dim3(3 * CDIM / 128, MROWS / 128), 256, GEMM_SMEM>>>(x, wqkvT, nullptr, qkvp);

    // 2) Causal flash attention (fp32)
    const size_t shm = 4 * 64 * STRD * sizeof(float);
    cudaFuncSetAttribute(flash_kernel, cudaFuncAttributeMaxDynamicSharedMemorySize, (int)shm);
    flash_kernel<<<dim3(SEQ / 64, BATCH * NHEAD), 128, shm>>>(qkvp, attp);

    // 3) Output projection + bias via mma.sync tf32
    gemm_mma<CDIM, true>
        <<<dim3(CDIM / 128, MROWS / 128), 256, GEMM_SMEM>>>(attp, wprojT, b_proj, out);
}

// round 4
// speedup vs baseline: 2.6694x; 1.9688x over previous
#include <cuda_runtime.h>
#include <cuda_bf16.h>
#include <math.h>
#include <stdint.h>

// Problem constants (B=2, T=2048, C=1024, H=16, D=64)
#define BATCH 2
#define SEQ   2048
#define CDIM  1024
#define NHEAD 16
#define HDIM  64
#define MROWS (BATCH*SEQ)          // 4096
#define KDIM  CDIM

// Scratch (device globals: sanctioned alloc-free scratch)
__device__ float g_qkv[(size_t)MROWS * 3 * CDIM];     // [4096, 3072]
__device__ float g_att[(size_t)MROWS * CDIM];         // [4096, 1024]
__device__ float g_wqkvT[(size_t)3 * CDIM * CDIM];    // [3072, 1024]
__device__ float g_wprojT[(size_t)CDIM * CDIM];       // [1024, 1024]

// ---------------------------------------------------------------------------
// helpers
// ---------------------------------------------------------------------------
__device__ __forceinline__ uint32_t smem_to_u32(const void* p) {
    uint32_t a;
    asm("{ .reg .u64 t; cvta.to.shared.u64 t, %1; cvt.u32.u64 %0, t; }" : "=r"(a) : "l"(p));
    return a;
}
__device__ __forceinline__ uint32_t tf32r(float v) {
    uint32_t r;
    asm("cvt.rna.tf32.f32 %0, %1;" : "=r"(r) : "f"(v));
    return r;
}
#define CP_ASYNC16(dst, src) \
    asm volatile("cp.async.cg.shared.global [%0], [%1], 16;" :: "r"(dst), "l"(src))
#define CP_COMMIT() asm volatile("cp.async.commit_group;" ::: "memory")
#define CP_WAIT(n)  asm volatile("cp.async.wait_group %0;" :: "n"(n) : "memory")

__device__ __forceinline__ void mma_tf32(float* c, const uint32_t* a, const uint32_t* b) {
    asm volatile(
        "mma.sync.aligned.m16n8k8.row.col.f32.tf32.tf32.f32 "
        "{%0,%1,%2,%3}, {%4,%5,%6,%7}, {%8,%9}, {%0,%1,%2,%3};"
        : "+f"(c[0]), "+f"(c[1]), "+f"(c[2]), "+f"(c[3])
        : "r"(a[0]), "r"(a[1]), "r"(a[2]), "r"(a[3]), "r"(b[0]), "r"(b[1]));
}

// ===========================================================================
// tf32 mma.sync GEMM (unchanged from R3-passing): C = A @ BT^T (+bias)
// ===========================================================================
#define TSTR 36
#define TILE_F (128 * TSTR)
#define GEMM_SMEM (4 * TILE_F * 4)

template<int Nn, bool BIAS>
__global__ __launch_bounds__(256) void gemm_mma(
    const float* __restrict__ A, const float* __restrict__ BT,
    const float* __restrict__ bias, float* __restrict__ C)
{
    extern __shared__ __align__(16) float smf[];
    float* sA[2] = { smf,              smf + 2 * TILE_F };
    float* sB[2] = { smf + TILE_F,     smf + 3 * TILE_F };
    const uint32_t sAu[2] = { smem_to_u32(sA[0]), smem_to_u32(sA[1]) };
    const uint32_t sBu[2] = { smem_to_u32(sB[0]), smem_to_u32(sB[1]) };

    const int tid = threadIdx.x, lane = tid & 31, wid = tid >> 5;
    const int m0 = blockIdx.y * 128, n0 = blockIdx.x * 128;
    const int mw = (wid & 3) * 32;
    const int nw = (wid >> 2) * 64;
    const int g = lane >> 2, t4 = lane & 3;

    const float* Ab = A + (size_t)m0 * KDIM;
    const float* Bb = BT + (size_t)n0 * KDIM;

    auto prefetch = [&](int kc, int s) {
        const int kb = kc * 32;
        #pragma unroll
        for (int q = 0; q < 4; q++) {
            const int f = tid + q * 256;
            const int row = f >> 3, c4 = f & 7;
            CP_ASYNC16(sAu[s] + row * (TSTR * 4) + c4 * 16,
                       Ab + (size_t)row * KDIM + kb + c4 * 4);
            CP_ASYNC16(sBu[s] + row * (TSTR * 4) + c4 * 16,
                       Bb + (size_t)row * KDIM + kb + c4 * 4);
        }
        CP_COMMIT();
    };

    float acc[2][8][4];
    #pragma unroll
    for (int i = 0; i < 2; i++)
        #pragma unroll
        for (int j = 0; j < 8; j++)
            #pragma unroll
            for (int q = 0; q < 4; q++) acc[i][j][q] = 0.f;

    prefetch(0, 0);
    prefetch(1, 1);

    for (int kc = 0; kc < 32; ++kc) {
        const int s = kc & 1;
        if (kc < 31) { CP_WAIT(1); } else { CP_WAIT(0); }
        __syncthreads();

        const float* __restrict__ As = sA[s];
        const float* __restrict__ Bs = sB[s];
        #pragma unroll
        for (int ks = 0; ks < 4; ++ks) {
            const int kb = ks * 8;
            uint32_t a[2][4], b[8][2];
            #pragma unroll
            for (int i = 0; i < 2; i++) {
                a[i][0] = tf32r(As[(mw + 16 * i + g) * TSTR + kb + t4]);
                a[i][1] = tf32r(As[(mw + 16 * i + g + 8) * TSTR + kb + t4]);
                a[i][2] = tf32r(As[(mw + 16 * i + g) * TSTR + kb + t4 + 4]);
                a[i][3] = tf32r(As[(mw + 16 * i + g + 8) * TSTR + kb + t4 + 4]);
            }
            #pragma unroll
            for (int j = 0; j < 8; j++) {
                b[j][0] = __float_as_uint(Bs[(nw + 8 * j + g) * TSTR + kb + t4]);
                b[j][1] = __float_as_uint(Bs[(nw + 8 * j + g) * TSTR + kb + t4 + 4]);
            }
            #pragma unroll
            for (int i = 0; i < 2; i++)
                #pragma unroll
                for (int j = 0; j < 8; j++)
                    mma_tf32(acc[i][j], a[i], b[j]);
        }
        __syncthreads();
        if (kc + 2 < 32) prefetch(kc + 2, s);
    }

    #pragma unroll
    for (int i = 0; i < 2; i++) {
        const int r0 = m0 + mw + 16 * i + g;
        const int r1 = r0 + 8;
        #pragma unroll
        for (int j = 0; j < 8; j++) {
            const int col = n0 + nw + 8 * j + 2 * t4;
            float2 bv = make_float2(0.f, 0.f);
            if (BIAS) bv = *(const float2*)(bias + col);
            *(float2*)(C + (size_t)r0 * Nn + col) =
                make_float2(acc[i][j][0] + bv.x, acc[i][j][1] + bv.y);
            *(float2*)(C + (size_t)r1 * Nn + col) =
                make_float2(acc[i][j][2] + bv.x, acc[i][j][3] + bv.y);
        }
    }
}

// ===========================================================================
// Transpose with tf32 rounding: in [R, Cc] -> out [Cc, R]
// ===========================================================================
__global__ __launch_bounds__(256) void transpose_tf32(
    const float* __restrict__ in, float* __restrict__ out, int R, int Cc)
{
    __shared__ float tile[32][33];
    const int x = blockIdx.x * 32 + threadIdx.x;
    const int y0 = blockIdx.y * 32;
    #pragma unroll
    for (int j = threadIdx.y; j < 32; j += 8)
        tile[j][threadIdx.x] = in[(size_t)(y0 + j) * Cc + x];
    __syncthreads();
    const int x2 = y0 + threadIdx.x;
    const int y2 = blockIdx.x * 32;
    #pragma unroll
    for (int j = threadIdx.y; j < 32; j += 8)
        ((uint32_t*)out)[(size_t)(y2 + j) * R + x2] = tf32r(tile[threadIdx.x][j]);
}

// ===========================================================================
// Flash attention on mma.sync tf32.
// Grid (32, 32): x -> q-tile (reversed), y -> b*h. 128 threads, 4 warps.
// Q tile 64 rows (16/warp), K/V tiles 64 keys.
// S = QK^T via error-compensated split (qh,ql x Khi,Klo; 3 mmas) -> fp32-accurate.
// PV in plain tf32 (P in [0,1]).
// smem: Khi/Klo/Vt 64x68 each + P 4x16x68  = 69632 B.
// ===========================================================================
#define FSTR 68
#define FLASH_SMEM (17408 * 4)

__global__ __launch_bounds__(128, 2) void flash_mma(
    const float* __restrict__ qkv, float* __restrict__ att)
{
    extern __shared__ __align__(16) float fs[];
    float* Khi = fs;
    float* Klo = fs + 64 * FSTR;
    float* Vt  = fs + 2 * 64 * FSTR;
    float* Pw  = fs + 3 * 64 * FSTR;      // + wid*16*FSTR

    const int tid = threadIdx.x, lane = tid & 31, wid = tid >> 5;
    const int g = lane >> 2, t4 = lane & 3;
    const int qt = (int)gridDim.x - 1 - (int)blockIdx.x;   // heavy tiles first
    const int bh = blockIdx.y;
    const int b = bh >> 4, h = bh & 15;

    const float* qb  = qkv + (size_t)b * SEQ * (3 * CDIM) + h * HDIM;
    const float* kbp = qb + CDIM;
    const float* vbp = qb + 2 * CDIM;
    const int qbase = qt * 64;
    const int rl0 = wid * 16 + g;          // tile-local rows
    const int rl1 = rl0 + 8;

    // --- Q fragments (scaled by 1/sqrt(D), hi/lo split) ---
    uint32_t qh[8][4], ql[8][4];
    #pragma unroll
    for (int ks = 0; ks < 8; ks++) {
        const int c0 = ks * 8 + t4;
        const float v[4] = {
            qb[(size_t)(qbase + rl0) * 3072 + c0]     * 0.125f,
            qb[(size_t)(qbase + rl1) * 3072 + c0]     * 0.125f,
            qb[(size_t)(qbase + rl0) * 3072 + c0 + 4] * 0.125f,
            qb[(size_t)(qbase + rl1) * 3072 + c0 + 4] * 0.125f };
        #pragma unroll
        for (int e = 0; e < 4; e++) {
            qh[ks][e] = tf32r(v[e]);
            ql[ks][e] = tf32r(v[e] - __uint_as_float(qh[ks][e]));
        }
    }

    float o[8][4];
    #pragma unroll
    for (int n = 0; n < 8; n++)
        #pragma unroll
        for (int e = 0; e < 4; e++) o[n][e] = 0.f;
    float mrow0 = -INFINITY, mrow1 = -INFINITY, lrow0 = 0.f, lrow1 = 0.f;

    for (int kt = 0; kt <= qt; ++kt) {
        __syncthreads();
        // --- load K (hi/lo split) and V (transposed, tf32) into smem ---
        const int kb0 = kt * 64;
        #pragma unroll 4
        for (int i = 0; i < 8; i++) {
            const int idx = tid + i * 128;
            const int key = idx >> 4, c4 = idx & 15;
            const float4 kv = *(const float4*)(kbp + (size_t)(kb0 + key) * 3072 + c4 * 4);
            uint4 hi, lo;
            hi.x = tf32r(kv.x); lo.x = tf32r(kv.x - __uint_as_float(hi.x));
            hi.y = tf32r(kv.y); lo.y = tf32r(kv.y - __uint_as_float(hi.y));
            hi.z = tf32r(kv.z); lo.z = tf32r(kv.z - __uint_as_float(hi.z));
            hi.w = tf32r(kv.w); lo.w = tf32r(kv.w - __uint_as_float(hi.w));
            *(uint4*)(Khi + key * FSTR + c4 * 4) = hi;
            *(uint4*)(Klo + key * FSTR + c4 * 4) = lo;
            const float4 vv = *(const float4*)(vbp + (size_t)(kb0 + key) * 3072 + c4 * 4);
            ((uint32_t*)Vt)[(c4 * 4 + 0) * FSTR + key] = tf32r(vv.x);
            ((uint32_t*)Vt)[(c4 * 4 + 1) * FSTR + key] = tf32r(vv.y);
            ((uint32_t*)Vt)[(c4 * 4 + 2) * FSTR + key] = tf32r(vv.z);
            ((uint32_t*)Vt)[(c4 * 4 + 3) * FSTR + key] = tf32r(vv.w);
        }
        __syncthreads();

        // --- S = Q K^T (split, fp32-accurate) ---
        float s[8][4];
        #pragma unroll
        for (int n = 0; n < 8; n++)
            #pragma unroll
            for (int e = 0; e < 4; e++) s[n][e] = 0.f;
        #pragma unroll
        for (int ks = 0; ks < 8; ks++) {
            const int kb = ks * 8 + t4;
            #pragma unroll
            for (int n = 0; n < 8; n++) {
                const int roff = (n * 8 + g) * FSTR + kb;
                uint32_t bhv[2] = { ((const uint32_t*)Khi)[roff], ((const uint32_t*)Khi)[roff + 4] };
                uint32_t blv[2] = { ((const uint32_t*)Klo)[roff], ((const uint32_t*)Klo)[roff + 4] };
                mma_tf32(s[n], qh[ks], bhv);
                mma_tf32(s[n], ql[ks], bhv);
                mma_tf32(s[n], qh[ks], blv);
            }
        }

        // --- causal mask (diagonal tile only) ---
        if (kt == qt) {
            #pragma unroll
            for (int n = 0; n < 8; n++) {
                const int c0 = n * 8 + 2 * t4;
                if (c0 > rl0)     s[n][0] = -INFINITY;
                if (c0 + 1 > rl0) s[n][1] = -INFINITY;
                if (c0 > rl1)     s[n][2] = -INFINITY;
                if (c0 + 1 > rl1) s[n][3] = -INFINITY;
            }
        }

        // --- online softmax (rows rl0, rl1) ---
        float rmax0 = -INFINITY, rmax1 = -INFINITY;
        #pragma unroll
        for (int n = 0; n < 8; n++) {
            rmax0 = fmaxf(rmax0, fmaxf(s[n][0], s[n][1]));
            rmax1 = fmaxf(rmax1, fmaxf(s[n][2], s[n][3]));
        }
        rmax0 = fmaxf(rmax0, __shfl_xor_sync(0xffffffffu, rmax0, 1));
        rmax0 = fmaxf(rmax0, __shfl_xor_sync(0xffffffffu, rmax0, 2));
        rmax1 = fmaxf(rmax1, __shfl_xor_sync(0xffffffffu, rmax1, 1));
        rmax1 = fmaxf(rmax1, __shfl_xor_sync(0xffffffffu, rmax1, 2));
        const float mnew0 = fmaxf(mrow0, rmax0);
        const float mnew1 = fmaxf(mrow1, rmax1);
        const float corr0 = __expf(mrow0 - mnew0);
        const float corr1 = __expf(mrow1 - mnew1);
        float ps0 = 0.f, ps1 = 0.f;
        #pragma unroll
        for (int n = 0; n < 8; n++) {
            s[n][0] = __expf(s[n][0] - mnew0);
            s[n][1] = __expf(s[n][1] - mnew0);
            s[n][2] = __expf(s[n][2] - mnew1);
            s[n][3] = __expf(s[n][3] - mnew1);
            ps0 += s[n][0] + s[n][1];
            ps1 += s[n][2] + s[n][3];
        }
        ps0 += __shfl_xor_sync(0xffffffffu, ps0, 1);
        ps0 += __shfl_xor_sync(0xffffffffu, ps0, 2);
        ps1 += __shfl_xor_sync(0xffffffffu, ps1, 1);
        ps1 += __shfl_xor_sync(0xffffffffu, ps1, 2);
        lrow0 = lrow0 * corr0 + ps0; mrow0 = mnew0;
        lrow1 = lrow1 * corr1 + ps1; mrow1 = mnew1;
        #pragma unroll
        for (int n = 0; n < 8; n++) {
            o[n][0] *= corr0; o[n][1] *= corr0;
            o[n][2] *= corr1; o[n][3] *= corr1;
        }

        // --- write P (tf32 bits) to per-warp smem strip ---
        uint32_t* P = (uint32_t*)(Pw + wid * 16 * FSTR);
        #pragma unroll
        for (int n = 0; n < 8; n++) {
            const int c0 = n * 8 + 2 * t4;
            *(uint2*)(P + g * FSTR + c0)       = make_uint2(tf32r(s[n][0]), tf32r(s[n][1]));
            *(uint2*)(P + (g + 8) * FSTR + c0) = make_uint2(tf32r(s[n][2]), tf32r(s[n][3]));
        }
        __syncwarp();

        // --- O += P @ V ---
        #pragma unroll
        for (int ks = 0; ks < 8; ks++) {
            const int kb = ks * 8 + t4;
            uint32_t a[4] = { P[g * FSTR + kb], P[(g + 8) * FSTR + kb],
                              P[g * FSTR + kb + 4], P[(g + 8) * FSTR + kb + 4] };
            #pragma unroll
            for (int n = 0; n < 8; n++) {
                const int roff = (n * 8 + g) * FSTR + kb;
                uint32_t bv[2] = { ((const uint32_t*)Vt)[roff], ((const uint32_t*)Vt)[roff + 4] };
                mma_tf32(o[n], a, bv);
            }
        }
    }

    // --- epilogue ---
    const float inv0 = 1.f / lrow0, inv1 = 1.f / lrow1;
    float* out0 = att + (size_t)(b * SEQ + qbase + rl0) * CDIM + h * HDIM;
    float* out1 = att + (size_t)(b * SEQ + qbase + rl1) * CDIM + h * HDIM;
    #pragma unroll
    for (int n = 0; n < 8; n++) {
        const int c0 = n * 8 + 2 * t4;
        *(float2*)(out0 + c0) = make_float2(o[n][0] * inv0, o[n][1] * inv0);
        *(float2*)(out1 + c0) = make_float2(o[n][2] * inv1, o[n][3] * inv1);
    }
}

// ===========================================================================
extern "C" void kernel_launch(void* const* d_in, const int* in_sizes, int n_in,
                              void* d_out, int out_size)
{
    const float* x      = (const float*)d_in[0];
    const float* w_qkv  = (const float*)d_in[1];
    const float* w_proj = (const float*)d_in[2];
    const float* b_proj = (const float*)d_in[3];
    float* out = (float*)d_out;

    float *qkvp, *attp, *wqkvT, *wprojT;
    cudaGetSymbolAddress((void**)&qkvp, g_qkv);
    cudaGetSymbolAddress((void**)&attp, g_att);
    cudaGetSymbolAddress((void**)&wqkvT, g_wqkvT);
    cudaGetSymbolAddress((void**)&wprojT, g_wprojT);

    cudaFuncSetAttribute(gemm_mma<3 * CDIM, false>,
                         cudaFuncAttributeMaxDynamicSharedMemorySize, GEMM_SMEM);
    cudaFuncSetAttribute(gemm_mma<CDIM, true>,
                         cudaFuncAttributeMaxDynamicSharedMemorySize, GEMM_SMEM);
    cudaFuncSetAttribute(flash_mma,
                         cudaFuncAttributeMaxDynamicSharedMemorySize, FLASH_SMEM);

    // 0) Pre-transpose + tf32-round weights
    transpose_tf32<<<dim3(3 * CDIM / 32, CDIM / 32), dim3(32, 8)>>>(w_qkv, wqkvT, CDIM, 3 * CDIM);
    transpose_tf32<<<dim3(CDIM / 32, CDIM / 32), dim3(32, 8)>>>(w_proj, wprojT, CDIM, CDIM);

    // 1) QKV projection via mma.sync tf32
    gemm_mma<3 * CDIM, false>
        <<<dim3(3 * CDIM / 128, MROWS / 128), 256, GEMM_SMEM>>>(x, wqkvT, nullptr, qkvp);

    // 2) Causal flash attention via mma.sync tf32 (compensated QK^T)
    flash_mma<<<dim3(SEQ / 64, BATCH * NHEAD), 128, FLASH_SMEM>>>(qkvp, attp);

    // 3) Output projection + bias via mma.sync tf32
    gemm_mma<CDIM, true>
        <<<dim3(CDIM / 128, MROWS / 128), 256, GEMM_SMEM>>>(attp, wprojT, b_proj, out);
}

// round 5
// speedup vs baseline: 2.8118x; 1.0533x over previous
#include <cuda_runtime.h>
#include <cuda_bf16.h>
#include <math.h>
#include <stdint.h>

// Problem constants (B=2, T=2048, C=1024, H=16, D=64)
#define BATCH 2
#define SEQ   2048
#define CDIM  1024
#define NHEAD 16
#define HDIM  64
#define MROWS (BATCH*SEQ)          // 4096
#define KDIM  CDIM

// Scratch (device globals: sanctioned alloc-free scratch)
__device__ float g_qkv[(size_t)MROWS * 3 * CDIM];     // [4096, 3072]
__device__ float g_att[(size_t)MROWS * CDIM];         // [4096, 1024]
__device__ float g_wqkvT[(size_t)3 * CDIM * CDIM];    // [3072, 1024]
__device__ float g_wprojT[(size_t)CDIM * CDIM];       // [1024, 1024]

// ---------------------------------------------------------------------------
// helpers
// ---------------------------------------------------------------------------
__device__ __forceinline__ uint32_t smem_to_u32(const void* p) {
    uint32_t a;
    asm("{ .reg .u64 t; cvta.to.shared.u64 t, %1; cvt.u32.u64 %0, t; }" : "=r"(a) : "l"(p));
    return a;
}
__device__ __forceinline__ uint32_t tf32r(float v) {
    uint32_t r;
    asm("cvt.rna.tf32.f32 %0, %1;" : "=r"(r) : "f"(v));
    return r;
}
#define CP_ASYNC16(dst, src) \
    asm volatile("cp.async.cg.shared.global [%0], [%1], 16;" :: "r"(dst), "l"(src))
#define CP_COMMIT() asm volatile("cp.async.commit_group;" ::: "memory")
#define CP_WAIT(n)  asm volatile("cp.async.wait_group %0;" :: "n"(n) : "memory")

__device__ __forceinline__ void mma_tf32(float* c, const uint32_t* a, const uint32_t* b) {
    asm volatile(
        "mma.sync.aligned.m16n8k8.row.col.f32.tf32.tf32.f32 "
        "{%0,%1,%2,%3}, {%4,%5,%6,%7}, {%8,%9}, {%0,%1,%2,%3};"
        : "+f"(c[0]), "+f"(c[1]), "+f"(c[2]), "+f"(c[3])
        : "r"(a[0]), "r"(a[1]), "r"(a[2]), "r"(a[3]), "r"(b[0]), "r"(b[1]));
}
__device__ __forceinline__ void mma_bf16(float* c, const uint32_t* a, const uint32_t* b) {
    asm volatile(
        "mma.sync.aligned.m16n8k16.row.col.f32.bf16.bf16.f32 "
        "{%0,%1,%2,%3}, {%4,%5,%6,%7}, {%8,%9}, {%0,%1,%2,%3};"
        : "+f"(c[0]), "+f"(c[1]), "+f"(c[2]), "+f"(c[3])
        : "r"(a[0]), "r"(a[1]), "r"(a[2]), "r"(a[3]), "r"(b[0]), "r"(b[1]));
}
// split (x,y) into bf16 hi/lo pairs packed as bf16x2 (x in low half = lower k)
__device__ __forceinline__ void split2(float x, float y, uint32_t& hi, uint32_t& lo) {
    __nv_bfloat16 hx = __float2bfloat16(x);
    __nv_bfloat16 hy = __float2bfloat16(y);
    float fx = __bfloat162float(hx), fy = __bfloat162float(hy);
    __nv_bfloat16 lx = __float2bfloat16(x - fx);
    __nv_bfloat16 ly = __float2bfloat16(y - fy);
    hi = (uint32_t)__bfloat16_as_ushort(hx) | ((uint32_t)__bfloat16_as_ushort(hy) << 16);
    lo = (uint32_t)__bfloat16_as_ushort(lx) | ((uint32_t)__bfloat16_as_ushort(ly) << 16);
}

// ===========================================================================
// tf32 mma.sync GEMM (unchanged, R3/R4-passing): C = A @ BT^T (+bias)
// ===========================================================================
#define TSTR 36
#define TILE_F (128 * TSTR)
#define GEMM_SMEM (4 * TILE_F * 4)

template<int Nn, bool BIAS>
__global__ __launch_bounds__(256) void gemm_mma(
    const float* __restrict__ A, const float* __restrict__ BT,
    const float* __restrict__ bias, float* __restrict__ C)
{
    extern __shared__ __align__(16) float smf[];
    float* sA[2] = { smf,              smf + 2 * TILE_F };
    float* sB[2] = { smf + TILE_F,     smf + 3 * TILE_F };
    const uint32_t sAu[2] = { smem_to_u32(sA[0]), smem_to_u32(sA[1]) };
    const uint32_t sBu[2] = { smem_to_u32(sB[0]), smem_to_u32(sB[1]) };

    const int tid = threadIdx.x, lane = tid & 31, wid = tid >> 5;
    const int m0 = blockIdx.y * 128, n0 = blockIdx.x * 128;
    const int mw = (wid & 3) * 32;
    const int nw = (wid >> 2) * 64;
    const int g = lane >> 2, t4 = lane & 3;

    const float* Ab = A + (size_t)m0 * KDIM;
    const float* Bb = BT + (size_t)n0 * KDIM;

    auto prefetch = [&](int kc, int s) {
        const int kb = kc * 32;
        #pragma unroll
        for (int q = 0; q < 4; q++) {
            const int f = tid + q * 256;
            const int row = f >> 3, c4 = f & 7;
            CP_ASYNC16(sAu[s] + row * (TSTR * 4) + c4 * 16,
                       Ab + (size_t)row * KDIM + kb + c4 * 4);
            CP_ASYNC16(sBu[s] + row * (TSTR * 4) + c4 * 16,
                       Bb + (size_t)row * KDIM + kb + c4 * 4);
        }
        CP_COMMIT();
    };

    float acc[2][8][4];
    #pragma unroll
    for (int i = 0; i < 2; i++)
        #pragma unroll
        for (int j = 0; j < 8; j++)
            #pragma unroll
            for (int q = 0; q < 4; q++) acc[i][j][q] = 0.f;

    prefetch(0, 0);
    prefetch(1, 1);

    for (int kc = 0; kc < 32; ++kc) {
        const int s = kc & 1;
        if (kc < 31) { CP_WAIT(1); } else { CP_WAIT(0); }
        __syncthreads();

        const float* __restrict__ As = sA[s];
        const float* __restrict__ Bs = sB[s];
        #pragma unroll
        for (int ks = 0; ks < 4; ++ks) {
            const int kb = ks * 8;
            uint32_t a[2][4], b[8][2];
            #pragma unroll
            for (int i = 0; i < 2; i++) {
                a[i][0] = tf32r(As[(mw + 16 * i + g) * TSTR + kb + t4]);
                a[i][1] = tf32r(As[(mw + 16 * i + g + 8) * TSTR + kb + t4]);
                a[i][2] = tf32r(As[(mw + 16 * i + g) * TSTR + kb + t4 + 4]);
                a[i][3] = tf32r(As[(mw + 16 * i + g + 8) * TSTR + kb + t4 + 4]);
            }
            #pragma unroll
            for (int j = 0; j < 8; j++) {
                b[j][0] = __float_as_uint(Bs[(nw + 8 * j + g) * TSTR + kb + t4]);
                b[j][1] = __float_as_uint(Bs[(nw + 8 * j + g) * TSTR + kb + t4 + 4]);
            }
            #pragma unroll
            for (int i = 0; i < 2; i++)
                #pragma unroll
                for (int j = 0; j < 8; j++)
                    mma_tf32(acc[i][j], a[i], b[j]);
        }
        __syncthreads();
        if (kc + 2 < 32) prefetch(kc + 2, s);
    }

    #pragma unroll
    for (int i = 0; i < 2; i++) {
        const int r0 = m0 + mw + 16 * i + g;
        const int r1 = r0 + 8;
        #pragma unroll
        for (int j = 0; j < 8; j++) {
            const int col = n0 + nw + 8 * j + 2 * t4;
            float2 bv = make_float2(0.f, 0.f);
            if (BIAS) bv = *(const float2*)(bias + col);
            *(float2*)(C + (size_t)r0 * Nn + col) =
                make_float2(acc[i][j][0] + bv.x, acc[i][j][1] + bv.y);
            *(float2*)(C + (size_t)r1 * Nn + col) =
                make_float2(acc[i][j][2] + bv.x, acc[i][j][3] + bv.y);
        }
    }
}

// ===========================================================================
// Transpose with tf32 rounding: in [R, Cc] -> out [Cc, R]
// ===========================================================================
__global__ __launch_bounds__(256) void transpose_tf32(
    const float* __restrict__ in, float* __restrict__ out, int R, int Cc)
{
    __shared__ float tile[32][33];
    const int x = blockIdx.x * 32 + threadIdx.x;
    const int y0 = blockIdx.y * 32;
    #pragma unroll
    for (int j = threadIdx.y; j < 32; j += 8)
        tile[j][threadIdx.x] = in[(size_t)(y0 + j) * Cc + x];
    __syncthreads();
    const int x2 = y0 + threadIdx.x;
    const int y2 = blockIdx.x * 32;
    #pragma unroll
    for (int j = threadIdx.y; j < 32; j += 8)
        ((uint32_t*)out)[(size_t)(y2 + j) * R + x2] = tf32r(tile[threadIdx.x][j]);
}

// ===========================================================================
// Flash attention on bf16 m16n8k16 with hi/lo error compensation.
// Grid (32, 32): x -> q-tile (reversed), y -> b*h. 128 threads, 4 warps.
// S  = qh*Kh + ql*Kh + qh*Kl  (fp32-grade logits)
// PV = Ph*Vh + Pl*Vh + Ph*Vl  (register-only P repack, no smem round trip)
// smem: Khi/Klo [64 keys][72 bf16] + Vhi/Vlo transposed [64 d][72 keys] = 36864 B
// ===========================================================================
#define KSTR 72
#define FLASH_SMEM (4 * 64 * KSTR * 2)

__global__ __launch_bounds__(128, 3) void flash_bf16(
    const float* __restrict__ qkv, float* __restrict__ att)
{
    extern __shared__ __align__(16) __nv_bfloat16 fsb[];
    __nv_bfloat16* Khi = fsb;                    // [64][KSTR] keys x d
    __nv_bfloat16* Klo = fsb + 64 * KSTR;
    __nv_bfloat16* Vhi = fsb + 2 * 64 * KSTR;    // [64][KSTR] d x keys (transposed)
    __nv_bfloat16* Vlo = fsb + 3 * 64 * KSTR;

    const int tid = threadIdx.x, lane = tid & 31, wid = tid >> 5;
    const int g = lane >> 2, t4 = lane & 3;
    const int qt = (int)gridDim.x - 1 - (int)blockIdx.x;   // heavy tiles first
    const int bh = blockIdx.y;
    const int b = bh >> 4, h = bh & 15;

    const float* qb  = qkv + (size_t)b * SEQ * (3 * CDIM) + h * HDIM;
    const float* kbp = qb + CDIM;
    const float* vbp = qb + 2 * CDIM;
    const int qbase = qt * 64;
    const int rl0 = wid * 16 + g;
    const int rl1 = rl0 + 8;

    // --- Q fragments: hi/lo bf16x2 for 4 k16-steps ---
    uint32_t qh[4][4], ql[4][4];
    {
        const float* q0 = qb + (size_t)(qbase + rl0) * 3072;
        const float* q1 = qb + (size_t)(qbase + rl1) * 3072;
        #pragma unroll
        for (int ks = 0; ks < 4; ks++) {
            const int d0 = ks * 16 + 2 * t4;
            float2 v;
            v = *(const float2*)(q0 + d0);
            split2(v.x * 0.125f, v.y * 0.125f, qh[ks][0], ql[ks][0]);
            v = *(const float2*)(q1 + d0);
            split2(v.x * 0.125f, v.y * 0.125f, qh[ks][1], ql[ks][1]);
            v = *(const float2*)(q0 + d0 + 8);
            split2(v.x * 0.125f, v.y * 0.125f, qh[ks][2], ql[ks][2]);
            v = *(const float2*)(q1 + d0 + 8);
            split2(v.x * 0.125f, v.y * 0.125f, qh[ks][3], ql[ks][3]);
        }
    }

    float o[8][4];
    #pragma unroll
    for (int n = 0; n < 8; n++)
        #pragma unroll
        for (int e = 0; e < 4; e++) o[n][e] = 0.f;
    float mrow0 = -INFINITY, mrow1 = -INFINITY, lrow0 = 0.f, lrow1 = 0.f;

    for (int kt = 0; kt <= qt; ++kt) {
        __syncthreads();
        const int kb0 = kt * 64;
        // --- K tile: [key][d], hi/lo split; coalesced loads, uint2 stores ---
        #pragma unroll 4
        for (int i = 0; i < 8; i++) {
            const int idx = tid + i * 128;
            const int key = idx >> 4, c4 = idx & 15;
            const float4 kv = *(const float4*)(kbp + (size_t)(kb0 + key) * 3072 + c4 * 4);
            uint32_t h0, l0, h1, l1;
            split2(kv.x, kv.y, h0, l0);
            split2(kv.z, kv.w, h1, l1);
            *(uint2*)(Khi + key * KSTR + c4 * 4) = make_uint2(h0, h1);
            *(uint2*)(Klo + key * KSTR + c4 * 4) = make_uint2(l0, l1);
        }
        // --- V tile: transposed to [d][key], hi/lo; conflict-free scalar stores ---
        #pragma unroll 4
        for (int i = 0; i < 8; i++) {
            const int idx = tid + i * 128;
            const int key = idx & 63, dg = idx >> 6;
            const float4 vv = *(const float4*)(vbp + (size_t)(kb0 + key) * 3072 + dg * 4);
            const float v[4] = { vv.x, vv.y, vv.z, vv.w };
            #pragma unroll
            for (int j = 0; j < 4; j++) {
                __nv_bfloat16 hb = __float2bfloat16(v[j]);
                __nv_bfloat16 lb = __float2bfloat16(v[j] - __bfloat162float(hb));
                Vhi[(dg * 4 + j) * KSTR + key] = hb;
                Vlo[(dg * 4 + j) * KSTR + key] = lb;
            }
        }
        __syncthreads();

        // --- S = Q K^T (compensated bf16) ---
        float s[8][4];
        #pragma unroll
        for (int n = 0; n < 8; n++)
            #pragma unroll
            for (int e = 0; e < 4; e++) s[n][e] = 0.f;
        #pragma unroll
        for (int ks = 0; ks < 4; ks++) {
            const int kb = ks * 16 + 2 * t4;
            #pragma unroll
            for (int n = 0; n < 8; n++) {
                const int roff = (8 * n + g) * KSTR + kb;
                uint32_t bh2[2] = { *(const uint32_t*)(Khi + roff),
                                    *(const uint32_t*)(Khi + roff + 8) };
                uint32_t bl2[2] = { *(const uint32_t*)(Klo + roff),
                                    *(const uint32_t*)(Klo + roff + 8) };
                mma_bf16(s[n], qh[ks], bh2);
                mma_bf16(s[n], ql[ks], bh2);
                mma_bf16(s[n], qh[ks], bl2);
            }
        }

        // --- causal mask (diagonal tile only) ---
        if (kt == qt) {
            #pragma unroll
            for (int n = 0; n < 8; n++) {
                const int c0 = n * 8 + 2 * t4;
                if (c0 > rl0)     s[n][0] = -INFINITY;
                if (c0 + 1 > rl0) s[n][1] = -INFINITY;
                if (c0 > rl1)     s[n][2] = -INFINITY;
                if (c0 + 1 > rl1) s[n][3] = -INFINITY;
            }
        }

        // --- online softmax ---
        float rmax0 = -INFINITY, rmax1 = -INFINITY;
        #pragma unroll
        for (int n = 0; n < 8; n++) {
            rmax0 = fmaxf(rmax0, fmaxf(s[n][0], s[n][1]));
            rmax1 = fmaxf(rmax1, fmaxf(s[n][2], s[n][3]));
        }
        rmax0 = fmaxf(rmax0, __shfl_xor_sync(0xffffffffu, rmax0, 1));
        rmax0 = fmaxf(rmax0, __shfl_xor_sync(0xffffffffu, rmax0, 2));
        rmax1 = fmaxf(rmax1, __shfl_xor_sync(0xffffffffu, rmax1, 1));
        rmax1 = fmaxf(rmax1, __shfl_xor_sync(0xffffffffu, rmax1, 2));
        const float mnew0 = fmaxf(mrow0, rmax0);
        const float mnew1 = fmaxf(mrow1, rmax1);
        const float corr0 = __expf(mrow0 - mnew0);
        const float corr1 = __expf(mrow1 - mnew1);
        float ps0 = 0.f, ps1 = 0.f;
        #pragma unroll
        for (int n = 0; n < 8; n++) {
            s[n][0] = __expf(s[n][0] - mnew0);
            s[n][1] = __expf(s[n][1] - mnew0);
            s[n][2] = __expf(s[n][2] - mnew1);
            s[n][3] = __expf(s[n][3] - mnew1);
            ps0 += s[n][0] + s[n][1];
            ps1 += s[n][2] + s[n][3];
        }
        ps0 += __shfl_xor_sync(0xffffffffu, ps0, 1);
        ps0 += __shfl_xor_sync(0xffffffffu, ps0, 2);
        ps1 += __shfl_xor_sync(0xffffffffu, ps1, 1);
        ps1 += __shfl_xor_sync(0xffffffffu, ps1, 2);
        lrow0 = lrow0 * corr0 + ps0; mrow0 = mnew0;
        lrow1 = lrow1 * corr1 + ps1; mrow1 = mnew1;
        #pragma unroll
        for (int n = 0; n < 8; n++) {
            o[n][0] *= corr0; o[n][1] *= corr0;
            o[n][2] *= corr1; o[n][3] *= corr1;
        }

        // --- O += P @ V : register-only P repack (acc layout == A-frag layout) ---
        #pragma unroll
        for (int j = 0; j < 4; j++) {
            const int kb = j * 16 + 2 * t4;
            uint32_t Ah[4], Al[4];
            split2(s[2 * j][0],     s[2 * j][1],     Ah[0], Al[0]);
            split2(s[2 * j][2],     s[2 * j][3],     Ah[1], Al[1]);
            split2(s[2 * j + 1][0], s[2 * j + 1][1], Ah[2], Al[2]);
            split2(s[2 * j + 1][2], s[2 * j + 1][3], Ah[3], Al[3]);
            #pragma unroll
            for (int n = 0; n < 8; n++) {
                const int roff = (8 * n + g) * KSTR + kb;
                uint32_t bh2[2] = { *(const uint32_t*)(Vhi + roff),
                                    *(const uint32_t*)(Vhi + roff + 8) };
                uint32_t bl2[2] = { *(const uint32_t*)(Vlo + roff),
                                    *(const uint32_t*)(Vlo + roff + 8) };
                mma_bf16(o[n], Ah, bh2);
                mma_bf16(o[n], Al, bh2);
                mma_bf16(o[n], Ah, bl2);
            }
        }
    }

    // --- epilogue ---
    const float inv0 = 1.f / lrow0, inv1 = 1.f / lrow1;
    float* out0 = att + (size_t)(b * SEQ + qbase + rl0) * CDIM + h * HDIM;
    float* out1 = att + (size_t)(b * SEQ + qbase + rl1) * CDIM + h * HDIM;
    #pragma unroll
    for (int n = 0; n < 8; n++) {
        const int c0 = n * 8 + 2 * t4;
        *(float2*)(out0 + c0) = make_float2(o[n][0] * inv0, o[n][1] * inv0);
        *(float2*)(out1 + c0) = make_float2(o[n][2] * inv1, o[n][3] * inv1);
    }
}

// ===========================================================================
extern "C" void kernel_launch(void* const* d_in, const int* in_sizes, int n_in,
                              void* d_out, int out_size)
{
    const float* x      = (const float*)d_in[0];
    const float* w_qkv  = (const float*)d_in[1];
    const float* w_proj = (const float*)d_in[2];
    const float* b_proj = (const float*)d_in[3];
    float* out = (float*)d_out;

    float *qkvp, *attp, *wqkvT, *wprojT;
    cudaGetSymbolAddress((void**)&qkvp, g_qkv);
    cudaGetSymbolAddress((void**)&attp, g_att);
    cudaGetSymbolAddress((void**)&wqkvT, g_wqkvT);
    cudaGetSymbolAddress((void**)&wprojT, g_wprojT);

    cudaFuncSetAttribute(gemm_mma<3 * CDIM, false>,
                         cudaFuncAttributeMaxDynamicSharedMemorySize, GEMM_SMEM);
    cudaFuncSetAttribute(gemm_mma<CDIM, true>,
                         cudaFuncAttributeMaxDynamicSharedMemorySize, GEMM_SMEM);
    cudaFuncSetAttribute(flash_bf16,
                         cudaFuncAttributeMaxDynamicSharedMemorySize, FLASH_SMEM);

    // 0) Pre-transpose + tf32-round weights
    transpose_tf32<<<dim3(3 * CDIM / 32, CDIM / 32), dim3(32, 8)>>>(w_qkv, wqkvT, CDIM, 3 * CDIM);
    transpose_tf32<<<dim3(CDIM / 32, CDIM / 32), dim3(32, 8)>>>(w_proj, wprojT, CDIM, CDIM);

    // 1) QKV projection via mma.sync tf32
    gemm_mma<3 * CDIM, false>
        <<<dim3(3 * CDIM / 128, MROWS / 128), 256, GEMM_SMEM>>>(x, wqkvT, nullptr, qkvp);

    // 2) Causal flash attention via compensated bf16 mma
    flash_bf16<<<dim3(SEQ / 64, BATCH * NHEAD), 128, FLASH_SMEM>>>(qkvp, attp);

    // 3) Output projection + bias via mma.sync tf32
    gemm_mma<CDIM, true>
        <<<dim3(CDIM / 128, MROWS / 128), 256, GEMM_SMEM>>>(attp, wprojT, b_proj, out);
}

// round 6
// speedup vs baseline: 2.8274x; 1.0056x over previous
#include <cuda_runtime.h>
#include <cuda_bf16.h>
#include <math.h>
#include <stdint.h>

// Problem constants (B=2, T=2048, C=1024, H=16, D=64)
#define BATCH 2
#define SEQ   2048
#define CDIM  1024
#define NHEAD 16
#define HDIM  64
#define MROWS (BATCH*SEQ)          // 4096
#define KDIM  CDIM

// Scratch (device globals: sanctioned alloc-free scratch)
__device__ float g_qkv[(size_t)MROWS * 3 * CDIM];     // [4096, 3072]
__device__ float g_att[(size_t)MROWS * CDIM];         // [4096, 1024]
__device__ float g_wqkvT[(size_t)3 * CDIM * CDIM];    // [3072, 1024]
__device__ float g_wprojT[(size_t)CDIM * CDIM];       // [1024, 1024]

// ---------------------------------------------------------------------------
// helpers
// ---------------------------------------------------------------------------
__device__ __forceinline__ uint32_t smem_to_u32(const void* p) {
    uint32_t a;
    asm("{ .reg .u64 t; cvta.to.shared.u64 t, %1; cvt.u32.u64 %0, t; }" : "=r"(a) : "l"(p));
    return a;
}
__device__ __forceinline__ uint32_t tf32r(float v) {
    uint32_t r;
    asm("cvt.rna.tf32.f32 %0, %1;" : "=r"(r) : "f"(v));
    return r;
}
#define CP_ASYNC16(dst, src) \
    asm volatile("cp.async.cg.shared.global [%0], [%1], 16;" :: "r"(dst), "l"(src))
#define CP_COMMIT() asm volatile("cp.async.commit_group;" ::: "memory")
#define CP_WAIT(n)  asm volatile("cp.async.wait_group %0;" :: "n"(n) : "memory")

__device__ __forceinline__ void mma_tf32(float* c, const uint32_t* a, const uint32_t* b) {
    asm volatile(
        "mma.sync.aligned.m16n8k8.row.col.f32.tf32.tf32.f32 "
        "{%0,%1,%2,%3}, {%4,%5,%6,%7}, {%8,%9}, {%0,%1,%2,%3};"
        : "+f"(c[0]), "+f"(c[1]), "+f"(c[2]), "+f"(c[3])
        : "r"(a[0]), "r"(a[1]), "r"(a[2]), "r"(a[3]), "r"(b[0]), "r"(b[1]));
}
__device__ __forceinline__ void mma_bf16(float* c, const uint32_t* a, const uint32_t* b) {
    asm volatile(
        "mma.sync.aligned.m16n8k16.row.col.f32.bf16.bf16.f32 "
        "{%0,%1,%2,%3}, {%4,%5,%6,%7}, {%8,%9}, {%0,%1,%2,%3};"
        : "+f"(c[0]), "+f"(c[1]), "+f"(c[2]), "+f"(c[3])
        : "r"(a[0]), "r"(a[1]), "r"(a[2]), "r"(a[3]), "r"(b[0]), "r"(b[1]));
}
// split (x,y) into bf16 hi/lo pairs packed as bf16x2 (x in low half = lower k)
__device__ __forceinline__ void split2(float x, float y, uint32_t& hi, uint32_t& lo) {
    __nv_bfloat16 hx = __float2bfloat16(x);
    __nv_bfloat16 hy = __float2bfloat16(y);
    float fx = __bfloat162float(hx), fy = __bfloat162float(hy);
    __nv_bfloat16 lx = __float2bfloat16(x - fx);
    __nv_bfloat16 ly = __float2bfloat16(y - fy);
    hi = (uint32_t)__bfloat16_as_ushort(hx) | ((uint32_t)__bfloat16_as_ushort(hy) << 16);
    lo = (uint32_t)__bfloat16_as_ushort(lx) | ((uint32_t)__bfloat16_as_ushort(ly) << 16);
}

// ===========================================================================
// tf32 mma.sync GEMM (unchanged, R3/R4-passing): C = A @ BT^T (+bias)
// ===========================================================================
#define TSTR 36
#define TILE_F (128 * TSTR)
#define GEMM_SMEM (4 * TILE_F * 4)

template<int Nn, bool BIAS>
__global__ __launch_bounds__(256) void gemm_mma(
    const float* __restrict__ A, const float* __restrict__ BT,
    const float* __restrict__ bias, float* __restrict__ C)
{
    extern __shared__ __align__(16) float smf[];
    float* sA[2] = { smf,              smf + 2 * TILE_F };
    float* sB[2] = { smf + TILE_F,     smf + 3 * TILE_F };
    const uint32_t sAu[2] = { smem_to_u32(sA[0]), smem_to_u32(sA[1]) };
    const uint32_t sBu[2] = { smem_to_u32(sB[0]), smem_to_u32(sB[1]) };

    const int tid = threadIdx.x, lane = tid & 31, wid = tid >> 5;
    const int m0 = blockIdx.y * 128, n0 = blockIdx.x * 128;
    const int mw = (wid & 3) * 32;
    const int nw = (wid >> 2) * 64;
    const int g = lane >> 2, t4 = lane & 3;

    const float* Ab = A + (size_t)m0 * KDIM;
    const float* Bb = BT + (size_t)n0 * KDIM;

    auto prefetch = [&](int kc, int s) {
        const int kb = kc * 32;
        #pragma unroll
        for (int q = 0; q < 4; q++) {
            const int f = tid + q * 256;
            const int row = f >> 3, c4 = f & 7;
            CP_ASYNC16(sAu[s] + row * (TSTR * 4) + c4 * 16,
                       Ab + (size_t)row * KDIM + kb + c4 * 4);
            CP_ASYNC16(sBu[s] + row * (TSTR * 4) + c4 * 16,
                       Bb + (size_t)row * KDIM + kb + c4 * 4);
        }
        CP_COMMIT();
    };

    float acc[2][8][4];
    #pragma unroll
    for (int i = 0; i < 2; i++)
        #pragma unroll
        for (int j = 0; j < 8; j++)
            #pragma unroll
            for (int q = 0; q < 4; q++) acc[i][j][q] = 0.f;

    prefetch(0, 0);
    prefetch(1, 1);

    for (int kc = 0; kc < 32; ++kc) {
        const int s = kc & 1;
        if (kc < 31) { CP_WAIT(1); } else { CP_WAIT(0); }
        __syncthreads();

        const float* __restrict__ As = sA[s];
        const float* __restrict__ Bs = sB[s];
        #pragma unroll
        for (int ks = 0; ks < 4; ++ks) {
            const int kb = ks * 8;
            uint32_t a[2][4], b[8][2];
            #pragma unroll
            for (int i = 0; i < 2; i++) {
                a[i][0] = tf32r(As[(mw + 16 * i + g) * TSTR + kb + t4]);
                a[i][1] = tf32r(As[(mw + 16 * i + g + 8) * TSTR + kb + t4]);
                a[i][2] = tf32r(As[(mw + 16 * i + g) * TSTR + kb + t4 + 4]);
                a[i][3] = tf32r(As[(mw + 16 * i + g + 8) * TSTR + kb + t4 + 4]);
            }
            #pragma unroll
            for (int j = 0; j < 8; j++) {
                b[j][0] = __float_as_uint(Bs[(nw + 8 * j + g) * TSTR + kb + t4]);
                b[j][1] = __float_as_uint(Bs[(nw + 8 * j + g) * TSTR + kb + t4 + 4]);
            }
            #pragma unroll
            for (int i = 0; i < 2; i++)
                #pragma unroll
                for (int j = 0; j < 8; j++)
                    mma_tf32(acc[i][j], a[i], b[j]);
        }
        __syncthreads();
        if (kc + 2 < 32) prefetch(kc + 2, s);
    }

    #pragma unroll
    for (int i = 0; i < 2; i++) {
        const int r0 = m0 + mw + 16 * i + g;
        const int r1 = r0 + 8;
        #pragma unroll
        for (int j = 0; j < 8; j++) {
            const int col = n0 + nw + 8 * j + 2 * t4;
            float2 bv = make_float2(0.f, 0.f);
            if (BIAS) bv = *(const float2*)(bias + col);
            *(float2*)(C + (size_t)r0 * Nn + col) =
                make_float2(acc[i][j][0] + bv.x, acc[i][j][1] + bv.y);
            *(float2*)(C + (size_t)r1 * Nn + col) =
                make_float2(acc[i][j][2] + bv.x, acc[i][j][3] + bv.y);
        }
    }
}

// ===========================================================================
// Transpose with tf32 rounding: in [R, Cc] -> out [Cc, R]
// ===========================================================================
__global__ __launch_bounds__(256) void transpose_tf32(
    const float* __restrict__ in, float* __restrict__ out, int R, int Cc)
{
    __shared__ float tile[32][33];
    const int x = blockIdx.x * 32 + threadIdx.x;
    const int y0 = blockIdx.y * 32;
    #pragma unroll
    for (int j = threadIdx.y; j < 32; j += 8)
        tile[j][threadIdx.x] = in[(size_t)(y0 + j) * Cc + x];
    __syncthreads();
    const int x2 = y0 + threadIdx.x;
    const int y2 = blockIdx.x * 32;
    #pragma unroll
    for (int j = threadIdx.y; j < 32; j += 8)
        ((uint32_t*)out)[(size_t)(y2 + j) * R + x2] = tf32r(tile[threadIdx.x][j]);
}

// ===========================================================================
// Flash attention on bf16 m16n8k16 with hi/lo error compensation.
// Grid (32, 32): x -> q-tile (reversed), y -> b*h. 128 threads, 4 warps.
// S  = qh*Kh + ql*Kh + qh*Kl  (fp32-grade logits)
// PV = Ph*Vh + Pl*Vh + Ph*Vl  (register-only P repack, no smem round trip)
// smem: Khi/Klo [64 keys][72 bf16] + Vhi/Vlo transposed [64 d][72 keys] = 36864 B
// ===========================================================================
#define KSTR 72
#define FLASH_SMEM (4 * 64 * KSTR * 2)

__global__ __launch_bounds__(128, 3) void flash_bf16(
    const float* __restrict__ qkv, float* __restrict__ att)
{
    extern __shared__ __align__(16) __nv_bfloat16 fsb[];
    __nv_bfloat16* Khi = fsb;                    // [64][KSTR] keys x d
    __nv_bfloat16* Klo = fsb + 64 * KSTR;
    __nv_bfloat16* Vhi = fsb + 2 * 64 * KSTR;    // [64][KSTR] d x keys (transposed)
    __nv_bfloat16* Vlo = fsb + 3 * 64 * KSTR;

    const int tid = threadIdx.x, lane = tid & 31, wid = tid >> 5;
    const int g = lane >> 2, t4 = lane & 3;
    const int qt = (int)gridDim.x - 1 - (int)blockIdx.x;   // heavy tiles first
    const int bh = blockIdx.y;
    const int b = bh >> 4, h = bh & 15;

    const float* qb  = qkv + (size_t)b * SEQ * (3 * CDIM) + h * HDIM;
    const float* kbp = qb + CDIM;
    const float* vbp = qb + 2 * CDIM;
    const int qbase = qt * 64;
    const int rl0 = wid * 16 + g;
    const int rl1 = rl0 + 8;

    // --- Q fragments: hi/lo bf16x2 for 4 k16-steps ---
    uint32_t qh[4][4], ql[4][4];
    {
        const float* q0 = qb + (size_t)(qbase + rl0) * 3072;
        const float* q1 = qb + (size_t)(qbase + rl1) * 3072;
        #pragma unroll
        for (int ks = 0; ks < 4; ks++) {
            const int d0 = ks * 16 + 2 * t4;
            float2 v;
            v = *(const float2*)(q0 + d0);
            split2(v.x * 0.125f, v.y * 0.125f, qh[ks][0], ql[ks][0]);
            v = *(const float2*)(q1 + d0);
            split2(v.x * 0.125f, v.y * 0.125f, qh[ks][1], ql[ks][1]);
            v = *(const float2*)(q0 + d0 + 8);
            split2(v.x * 0.125f, v.y * 0.125f, qh[ks][2], ql[ks][2]);
            v = *(const float2*)(q1 + d0 + 8);
            split2(v.x * 0.125f, v.y * 0.125f, qh[ks][3], ql[ks][3]);
        }
    }

    float o[8][4];
    #pragma unroll
    for (int n = 0; n < 8; n++)
        #pragma unroll
        for (int e = 0; e < 4; e++) o[n][e] = 0.f;
    float mrow0 = -INFINITY, mrow1 = -INFINITY, lrow0 = 0.f, lrow1 = 0.f;

    for (int kt = 0; kt <= qt; ++kt) {
        __syncthreads();
        const int kb0 = kt * 64;
        // --- K tile: [key][d], hi/lo split; coalesced loads, uint2 stores ---
        #pragma unroll 4
        for (int i = 0; i < 8; i++) {
            const int idx = tid + i * 128;
            const int key = idx >> 4, c4 = idx & 15;
            const float4 kv = *(const float4*)(kbp + (size_t)(kb0 + key) * 3072 + c4 * 4);
            uint32_t h0, l0, h1, l1;
            split2(kv.x, kv.y, h0, l0);
            split2(kv.z, kv.w, h1, l1);
            *(uint2*)(Khi + key * KSTR + c4 * 4) = make_uint2(h0, h1);
            *(uint2*)(Klo + key * KSTR + c4 * 4) = make_uint2(l0, l1);
        }
        // --- V tile: transposed to [d][key], hi/lo; conflict-free scalar stores ---
        #pragma unroll 4
        for (int i = 0; i < 8; i++) {
            const int idx = tid + i * 128;
            const int key = idx & 63, dg = idx >> 6;
            const float4 vv = *(const float4*)(vbp + (size_t)(kb0 + key) * 3072 + dg * 4);
            const float v[4] = { vv.x, vv.y, vv.z, vv.w };
            #pragma unroll
            for (int j = 0; j < 4; j++) {
                __nv_bfloat16 hb = __float2bfloat16(v[j]);
                __nv_bfloat16 lb = __float2bfloat16(v[j] - __bfloat162float(hb));
                Vhi[(dg * 4 + j) * KSTR + key] = hb;
                Vlo[(dg * 4 + j) * KSTR + key] = lb;
            }
        }
        __syncthreads();

        // --- S = Q K^T (compensated bf16) ---
        float s[8][4];
        #pragma unroll
        for (int n = 0; n < 8; n++)
            #pragma unroll
            for (int e = 0; e < 4; e++) s[n][e] = 0.f;
        #pragma unroll
        for (int ks = 0; ks < 4; ks++) {
            const int kb = ks * 16 + 2 * t4;
            #pragma unroll
            for (int n = 0; n < 8; n++) {
                const int roff = (8 * n + g) * KSTR + kb;
                uint32_t bh2[2] = { *(const uint32_t*)(Khi + roff),
                                    *(const uint32_t*)(Khi + roff + 8) };
                uint32_t bl2[2] = { *(const uint32_t*)(Klo + roff),
                                    *(const uint32_t*)(Klo + roff + 8) };
                mma_bf16(s[n], qh[ks], bh2);
                mma_bf16(s[n], ql[ks], bh2);
                mma_bf16(s[n], qh[ks], bl2);
            }
        }

        // --- causal mask (diagonal tile only) ---
        if (kt == qt) {
            #pragma unroll
            for (int n = 0; n < 8; n++) {
                const int c0 = n * 8 + 2 * t4;
                if (c0 > rl0)     s[n][0] = -INFINITY;
                if (c0 + 1 > rl0) s[n][1] = -INFINITY;
                if (c0 > rl1)     s[n][2] = -INFINITY;
                if (c0 + 1 > rl1) s[n][3] = -INFINITY;
            }
        }

        // --- online softmax ---
        float rmax0 = -INFINITY, rmax1 = -INFINITY;
        #pragma unroll
        for (int n = 0; n < 8; n++) {
            rmax0 = fmaxf(rmax0, fmaxf(s[n][0], s[n][1]));
            rmax1 = fmaxf(rmax1, fmaxf(s[n][2], s[n][3]));
        }
        rmax0 = fmaxf(rmax0, __shfl_xor_sync(0xffffffffu, rmax0, 1));
        rmax0 = fmaxf(rmax0, __shfl_xor_sync(0xffffffffu, rmax0, 2));
        rmax1 = fmaxf(rmax1, __shfl_xor_sync(0xffffffffu, rmax1, 1));
        rmax1 = fmaxf(rmax1, __shfl_xor_sync(0xffffffffu, rmax1, 2));
        const float mnew0 = fmaxf(mrow0, rmax0);
        const float mnew1 = fmaxf(mrow1, rmax1);
        const float corr0 = __expf(mrow0 - mnew0);
        const float corr1 = __expf(mrow1 - mnew1);
        float ps0 = 0.f, ps1 = 0.f;
        #pragma unroll
        for (int n = 0; n < 8; n++) {
            s[n][0] = __expf(s[n][0] - mnew0);
            s[n][1] = __expf(s[n][1] - mnew0);
            s[n][2] = __expf(s[n][2] - mnew1);
            s[n][3] = __expf(s[n][3] - mnew1);
            ps0 += s[n][0] + s[n][1];
            ps1 += s[n][2] + s[n][3];
        }
        ps0 += __shfl_xor_sync(0xffffffffu, ps0, 1);
        ps0 += __shfl_xor_sync(0xffffffffu, ps0, 2);
        ps1 += __shfl_xor_sync(0xffffffffu, ps1, 1);
        ps1 += __shfl_xor_sync(0xffffffffu, ps1, 2);
        lrow0 = lrow0 * corr0 + ps0; mrow0 = mnew0;
        lrow1 = lrow1 * corr1 + ps1; mrow1 = mnew1;
        #pragma unroll
        for (int n = 0; n < 8; n++) {
            o[n][0] *= corr0; o[n][1] *= corr0;
            o[n][2] *= corr1; o[n][3] *= corr1;
        }

        // --- O += P @ V : register-only P repack (acc layout == A-frag layout) ---
        #pragma unroll
        for (int j = 0; j < 4; j++) {
            const int kb = j * 16 + 2 * t4;
            uint32_t Ah[4], Al[4];
            split2(s[2 * j][0],     s[2 * j][1],     Ah[0], Al[0]);
            split2(s[2 * j][2],     s[2 * j][3],     Ah[1], Al[1]);
            split2(s[2 * j + 1][0], s[2 * j + 1][1], Ah[2], Al[2]);
            split2(s[2 * j + 1][2], s[2 * j + 1][3], Ah[3], Al[3]);
            #pragma unroll
            for (int n = 0; n < 8; n++) {
                const int roff = (8 * n + g) * KSTR + kb;
                uint32_t bh2[2] = { *(const uint32_t*)(Vhi + roff),
                                    *(const uint32_t*)(Vhi + roff + 8) };
                uint32_t bl2[2] = { *(const uint32_t*)(Vlo + roff),
                                    *(const uint32_t*)(Vlo + roff + 8) };
                mma_bf16(o[n], Ah, bh2);
                mma_bf16(o[n], Al, bh2);
                mma_bf16(o[n], Ah, bl2);
            }
        }
    }

    // --- epilogue ---
    const float inv0 = 1.f / lrow0, inv1 = 1.f / lrow1;
    float* out0 = att + (size_t)(b * SEQ + qbase + rl0) * CDIM + h * HDIM;
    float* out1 = att + (size_t)(b * SEQ + qbase + rl1) * CDIM + h * HDIM;
    #pragma unroll
    for (int n = 0; n < 8; n++) {
        const int c0 = n * 8 + 2 * t4;
        *(float2*)(out0 + c0) = make_float2(o[n][0] * inv0, o[n][1] * inv0);
        *(float2*)(out1 + c0) = make_float2(o[n][2] * inv1, o[n][3] * inv1);
    }
}

// ===========================================================================
extern "C" void kernel_launch(void* const* d_in, const int* in_sizes, int n_in,
                              void* d_out, int out_size)
{
    const float* x      = (const float*)d_in[0];
    const float* w_qkv  = (const float*)d_in[1];
    const float* w_proj = (const float*)d_in[2];
    const float* b_proj = (const float*)d_in[3];
    float* out = (float*)d_out;

    float *qkvp, *attp, *wqkvT, *wprojT;
    cudaGetSymbolAddress((void**)&qkvp, g_qkv);
    cudaGetSymbolAddress((void**)&attp, g_att);
    cudaGetSymbolAddress((void**)&wqkvT, g_wqkvT);
    cudaGetSymbolAddress((void**)&wprojT, g_wprojT);

    cudaFuncSetAttribute(gemm_mma<3 * CDIM, false>,
                         cudaFuncAttributeMaxDynamicSharedMemorySize, GEMM_SMEM);
    cudaFuncSetAttribute(gemm_mma<CDIM, true>,
                         cudaFuncAttributeMaxDynamicSharedMemorySize, GEMM_SMEM);
    cudaFuncSetAttribute(flash_bf16,
                         cudaFuncAttributeMaxDynamicSharedMemorySize, FLASH_SMEM);

    // 0) Pre-transpose + tf32-round weights
    transpose_tf32<<<dim3(3 * CDIM / 32, CDIM / 32), dim3(32, 8)>>>(w_qkv, wqkvT, CDIM, 3 * CDIM);
    transpose_tf32<<<dim3(CDIM / 32, CDIM / 32), dim3(32, 8)>>>(w_proj, wprojT, CDIM, CDIM);

    // 1) QKV projection via mma.sync tf32
    gemm_mma<3 * CDIM, false>
        <<<dim3(3 * CDIM / 128, MROWS / 128), 256, GEMM_SMEM>>>(x, wqkvT, nullptr, qkvp);

    // 2) Causal flash attention via compensated bf16 mma
    flash_bf16<<<dim3(SEQ / 64, BATCH * NHEAD), 128, FLASH_SMEM>>>(qkvp, attp);

    // 3) Output projection + bias via mma.sync tf32
    gemm_mma<CDIM, true>
        <<<dim3(CDIM / 128, MROWS / 128), 256, GEMM_SMEM>>>(attp, wprojT, b_proj, out);
}

// round 7
// speedup vs baseline: 2.8382x; 1.0038x over previous
#include <cuda_runtime.h>
#include <cuda_bf16.h>
#include <math.h>
#include <stdint.h>

// Problem constants (B=2, T=2048, C=1024, H=16, D=64)
#define BATCH 2
#define SEQ   2048
#define CDIM  1024
#define NHEAD 16
#define HDIM  64
#define MROWS (BATCH*SEQ)          // 4096
#define KDIM  CDIM

// Scratch (device globals: sanctioned alloc-free scratch)
__device__ float g_qkv[(size_t)MROWS * 3 * CDIM];     // [4096, 3072]
__device__ float g_att[(size_t)MROWS * CDIM];         // [4096, 1024]
__device__ float g_wqkvT[(size_t)3 * CDIM * CDIM];    // [3072, 1024]
__device__ float g_wprojT[(size_t)CDIM * CDIM];       // [1024, 1024]

// ---------------------------------------------------------------------------
// helpers
// ---------------------------------------------------------------------------
__device__ __forceinline__ uint32_t smem_to_u32(const void* p) {
    uint32_t a;
    asm("{ .reg .u64 t; cvta.to.shared.u64 t, %1; cvt.u32.u64 %0, t; }" : "=r"(a) : "l"(p));
    return a;
}
__device__ __forceinline__ uint32_t tf32r(float v) {
    uint32_t r;
    asm("cvt.rna.tf32.f32 %0, %1;" : "=r"(r) : "f"(v));
    return r;
}
#define CP_ASYNC16(dst, src) \
    asm volatile("cp.async.cg.shared.global [%0], [%1], 16;" :: "r"(dst), "l"(src))
#define CP_COMMIT() asm volatile("cp.async.commit_group;" ::: "memory")
#define CP_WAIT(n)  asm volatile("cp.async.wait_group %0;" :: "n"(n) : "memory")

__device__ __forceinline__ void mma_tf32(float* c, const uint32_t* a, const uint32_t* b) {
    asm volatile(
        "mma.sync.aligned.m16n8k8.row.col.f32.tf32.tf32.f32 "
        "{%0,%1,%2,%3}, {%4,%5,%6,%7}, {%8,%9}, {%0,%1,%2,%3};"
        : "+f"(c[0]), "+f"(c[1]), "+f"(c[2]), "+f"(c[3])
        : "r"(a[0]), "r"(a[1]), "r"(a[2]), "r"(a[3]), "r"(b[0]), "r"(b[1]));
}
__device__ __forceinline__ void mma_bf16(float* c, const uint32_t* a, const uint32_t* b) {
    asm volatile(
        "mma.sync.aligned.m16n8k16.row.col.f32.bf16.bf16.f32 "
        "{%0,%1,%2,%3}, {%4,%5,%6,%7}, {%8,%9}, {%0,%1,%2,%3};"
        : "+f"(c[0]), "+f"(c[1]), "+f"(c[2]), "+f"(c[3])
        : "r"(a[0]), "r"(a[1]), "r"(a[2]), "r"(a[3]), "r"(b[0]), "r"(b[1]));
}
// split (x,y) into bf16 hi/lo pairs packed as bf16x2 (x in low half = lower k)
__device__ __forceinline__ void split2(float x, float y, uint32_t& hi, uint32_t& lo) {
    __nv_bfloat16 hx = __float2bfloat16(x);
    __nv_bfloat16 hy = __float2bfloat16(y);
    float fx = __bfloat162float(hx), fy = __bfloat162float(hy);
    __nv_bfloat16 lx = __float2bfloat16(x - fx);
    __nv_bfloat16 ly = __float2bfloat16(y - fy);
    hi = (uint32_t)__bfloat16_as_ushort(hx) | ((uint32_t)__bfloat16_as_ushort(hy) << 16);
    lo = (uint32_t)__bfloat16_as_ushort(lx) | ((uint32_t)__bfloat16_as_ushort(ly) << 16);
}

// ===========================================================================
// tf32 mma.sync GEMM (unchanged, R3/R4-passing): C = A @ BT^T (+bias)
// ===========================================================================
#define TSTR 36
#define TILE_F (128 * TSTR)
#define GEMM_SMEM (4 * TILE_F * 4)

template<int Nn, bool BIAS>
__global__ __launch_bounds__(256) void gemm_mma(
    const float* __restrict__ A, const float* __restrict__ BT,
    const float* __restrict__ bias, float* __restrict__ C)
{
    extern __shared__ __align__(16) float smf[];
    float* sA[2] = { smf,              smf + 2 * TILE_F };
    float* sB[2] = { smf + TILE_F,     smf + 3 * TILE_F };
    const uint32_t sAu[2] = { smem_to_u32(sA[0]), smem_to_u32(sA[1]) };
    const uint32_t sBu[2] = { smem_to_u32(sB[0]), smem_to_u32(sB[1]) };

    const int tid = threadIdx.x, lane = tid & 31, wid = tid >> 5;
    const int m0 = blockIdx.y * 128, n0 = blockIdx.x * 128;
    const int mw = (wid & 3) * 32;
    const int nw = (wid >> 2) * 64;
    const int g = lane >> 2, t4 = lane & 3;

    const float* Ab = A + (size_t)m0 * KDIM;
    const float* Bb = BT + (size_t)n0 * KDIM;

    auto prefetch = [&](int kc, int s) {
        const int kb = kc * 32;
        #pragma unroll
        for (int q = 0; q < 4; q++) {
            const int f = tid + q * 256;
            const int row = f >> 3, c4 = f & 7;
            CP_ASYNC16(sAu[s] + row * (TSTR * 4) + c4 * 16,
                       Ab + (size_t)row * KDIM + kb + c4 * 4);
            CP_ASYNC16(sBu[s] + row * (TSTR * 4) + c4 * 16,
                       Bb + (size_t)row * KDIM + kb + c4 * 4);
        }
        CP_COMMIT();
    };

    float acc[2][8][4];
    #pragma unroll
    for (int i = 0; i < 2; i++)
        #pragma unroll
        for (int j = 0; j < 8; j++)
            #pragma unroll
            for (int q = 0; q < 4; q++) acc[i][j][q] = 0.f;

    prefetch(0, 0);
    prefetch(1, 1);

    for (int kc = 0; kc < 32; ++kc) {
        const int s = kc & 1;
        if (kc < 31) { CP_WAIT(1); } else { CP_WAIT(0); }
        __syncthreads();

        const float* __restrict__ As = sA[s];
        const float* __restrict__ Bs = sB[s];
        #pragma unroll
        for (int ks = 0; ks < 4; ++ks) {
            const int kb = ks * 8;
            uint32_t a[2][4], b[8][2];
            #pragma unroll
            for (int i = 0; i < 2; i++) {
                a[i][0] = tf32r(As[(mw + 16 * i + g) * TSTR + kb + t4]);
                a[i][1] = tf32r(As[(mw + 16 * i + g + 8) * TSTR + kb + t4]);
                a[i][2] = tf32r(As[(mw + 16 * i + g) * TSTR + kb + t4 + 4]);
                a[i][3] = tf32r(As[(mw + 16 * i + g + 8) * TSTR + kb + t4 + 4]);
            }
            #pragma unroll
            for (int j = 0; j < 8; j++) {
                b[j][0] = __float_as_uint(Bs[(nw + 8 * j + g) * TSTR + kb + t4]);
                b[j][1] = __float_as_uint(Bs[(nw + 8 * j + g) * TSTR + kb + t4 + 4]);
            }
            #pragma unroll
            for (int i = 0; i < 2; i++)
                #pragma unroll
                for (int j = 0; j < 8; j++)
                    mma_tf32(acc[i][j], a[i], b[j]);
        }
        __syncthreads();
        if (kc + 2 < 32) prefetch(kc + 2, s);
    }

    #pragma unroll
    for (int i = 0; i < 2; i++) {
        const int r0 = m0 + mw + 16 * i + g;
        const int r1 = r0 + 8;
        #pragma unroll
        for (int j = 0; j < 8; j++) {
            const int col = n0 + nw + 8 * j + 2 * t4;
            float2 bv = make_float2(0.f, 0.f);
            if (BIAS) bv = *(const float2*)(bias + col);
            *(float2*)(C + (size_t)r0 * Nn + col) =
                make_float2(acc[i][j][0] + bv.x, acc[i][j][1] + bv.y);
            *(float2*)(C + (size_t)r1 * Nn + col) =
                make_float2(acc[i][j][2] + bv.x, acc[i][j][3] + bv.y);
        }
    }
}

// ===========================================================================
// Transpose with tf32 rounding: in [R, Cc] -> out [Cc, R]
// ===========================================================================
__global__ __launch_bounds__(256) void transpose_tf32(
    const float* __restrict__ in, float* __restrict__ out, int R, int Cc)
{
    __shared__ float tile[32][33];
    const int x = blockIdx.x * 32 + threadIdx.x;
    const int y0 = blockIdx.y * 32;
    #pragma unroll
    for (int j = threadIdx.y; j < 32; j += 8)
        tile[j][threadIdx.x] = in[(size_t)(y0 + j) * Cc + x];
    __syncthreads();
    const int x2 = y0 + threadIdx.x;
    const int y2 = blockIdx.x * 32;
    #pragma unroll
    for (int j = threadIdx.y; j < 32; j += 8)
        ((uint32_t*)out)[(size_t)(y2 + j) * R + x2] = tf32r(tile[threadIdx.x][j]);
}

// ===========================================================================
// Flash attention on bf16 m16n8k16 with hi/lo error compensation.
// Grid (32, 32): x -> q-tile (reversed), y -> b*h. 128 threads, 4 warps.
// S  = qh*Kh + ql*Kh + qh*Kl  (fp32-grade logits)
// PV = Ph*Vh + Pl*Vh + Ph*Vl  (register-only P repack, no smem round trip)
// smem: Khi/Klo [64 keys][72 bf16] + Vhi/Vlo transposed [64 d][72 keys] = 36864 B
// ===========================================================================
#define KSTR 72
#define FLASH_SMEM (4 * 64 * KSTR * 2)

__global__ __launch_bounds__(128, 3) void flash_bf16(
    const float* __restrict__ qkv, float* __restrict__ att)
{
    extern __shared__ __align__(16) __nv_bfloat16 fsb[];
    __nv_bfloat16* Khi = fsb;                    // [64][KSTR] keys x d
    __nv_bfloat16* Klo = fsb + 64 * KSTR;
    __nv_bfloat16* Vhi = fsb + 2 * 64 * KSTR;    // [64][KSTR] d x keys (transposed)
    __nv_bfloat16* Vlo = fsb + 3 * 64 * KSTR;

    const int tid = threadIdx.x, lane = tid & 31, wid = tid >> 5;
    const int g = lane >> 2, t4 = lane & 3;
    const int qt = (int)gridDim.x - 1 - (int)blockIdx.x;   // heavy tiles first
    const int bh = blockIdx.y;
    const int b = bh >> 4, h = bh & 15;

    const float* qb  = qkv + (size_t)b * SEQ * (3 * CDIM) + h * HDIM;
    const float* kbp = qb + CDIM;
    const float* vbp = qb + 2 * CDIM;
    const int qbase = qt * 64;
    const int rl0 = wid * 16 + g;
    const int rl1 = rl0 + 8;

    // --- Q fragments: hi/lo bf16x2 for 4 k16-steps ---
    uint32_t qh[4][4], ql[4][4];
    {
        const float* q0 = qb + (size_t)(qbase + rl0) * 3072;
        const float* q1 = qb + (size_t)(qbase + rl1) * 3072;
        #pragma unroll
        for (int ks = 0; ks < 4; ks++) {
            const int d0 = ks * 16 + 2 * t4;
            float2 v;
            v = *(const float2*)(q0 + d0);
            split2(v.x * 0.125f, v.y * 0.125f, qh[ks][0], ql[ks][0]);
            v = *(const float2*)(q1 + d0);
            split2(v.x * 0.125f, v.y * 0.125f, qh[ks][1], ql[ks][1]);
            v = *(const float2*)(q0 + d0 + 8);
            split2(v.x * 0.125f, v.y * 0.125f, qh[ks][2], ql[ks][2]);
            v = *(const float2*)(q1 + d0 + 8);
            split2(v.x * 0.125f, v.y * 0.125f, qh[ks][3], ql[ks][3]);
        }
    }

    float o[8][4];
    #pragma unroll
    for (int n = 0; n < 8; n++)
        #pragma unroll
        for (int e = 0; e < 4; e++) o[n][e] = 0.f;
    float mrow0 = -INFINITY, mrow1 = -INFINITY, lrow0 = 0.f, lrow1 = 0.f;

    for (int kt = 0; kt <= qt; ++kt) {
        __syncthreads();
        const int kb0 = kt * 64;
        // --- K tile: [key][d], hi/lo split; coalesced loads, uint2 stores ---
        #pragma unroll 4
        for (int i = 0; i < 8; i++) {
            const int idx = tid + i * 128;
            const int key = idx >> 4, c4 = idx & 15;
            const float4 kv = *(const float4*)(kbp + (size_t)(kb0 + key) * 3072 + c4 * 4);
            uint32_t h0, l0, h1, l1;
            split2(kv.x, kv.y, h0, l0);
            split2(kv.z, kv.w, h1, l1);
            *(uint2*)(Khi + key * KSTR + c4 * 4) = make_uint2(h0, h1);
            *(uint2*)(Klo + key * KSTR + c4 * 4) = make_uint2(l0, l1);
        }
        // --- V tile: transposed to [d][key], hi/lo; conflict-free scalar stores ---
        #pragma unroll 4
        for (int i = 0; i < 8; i++) {
            const int idx = tid + i * 128;
            const int key = idx & 63, dg = idx >> 6;
            const float4 vv = *(const float4*)(vbp + (size_t)(kb0 + key) * 3072 + dg * 4);
            const float v[4] = { vv.x, vv.y, vv.z, vv.w };
            #pragma unroll
            for (int j = 0; j < 4; j++) {
                __nv_bfloat16 hb = __float2bfloat16(v[j]);
                __nv_bfloat16 lb = __float2bfloat16(v[j] - __bfloat162float(hb));
                Vhi[(dg * 4 + j) * KSTR + key] = hb;
                Vlo[(dg * 4 + j) * KSTR + key] = lb;
            }
        }
        __syncthreads();

        // --- S = Q K^T (compensated bf16) ---
        float s[8][4];
        #pragma unroll
        for (int n = 0; n < 8; n++)
            #pragma unroll
            for (int e = 0; e < 4; e++) s[n][e] = 0.f;
        #pragma unroll
        for (int ks = 0; ks < 4; ks++) {
            const int kb = ks * 16 + 2 * t4;
            #pragma unroll
            for (int n = 0; n < 8; n++) {
                const int roff = (8 * n + g) * KSTR + kb;
                uint32_t bh2[2] = { *(const uint32_t*)(Khi + roff),
                                    *(const uint32_t*)(Khi + roff + 8) };
                uint32_t bl2[2] = { *(const uint32_t*)(Klo + roff),
                                    *(const uint32_t*)(Klo + roff + 8) };
                mma_bf16(s[n], qh[ks], bh2);
                mma_bf16(s[n], ql[ks], bh2);
                mma_bf16(s[n], qh[ks], bl2);
            }
        }

        // --- causal mask (diagonal tile only) ---
        if (kt == qt) {
            #pragma unroll
            for (int n = 0; n < 8; n++) {
                const int c0 = n * 8 + 2 * t4;
                if (c0 > rl0)     s[n][0] = -INFINITY;
                if (c0 + 1 > rl0) s[n][1] = -INFINITY;
                if (c0 > rl1)     s[n][2] = -INFINITY;
                if (c0 + 1 > rl1) s[n][3] = -INFINITY;
            }
        }

        // --- online softmax ---
        float rmax0 = -INFINITY, rmax1 = -INFINITY;
        #pragma unroll
        for (int n = 0; n < 8; n++) {
            rmax0 = fmaxf(rmax0, fmaxf(s[n][0], s[n][1]));
            rmax1 = fmaxf(rmax1, fmaxf(s[n][2], s[n][3]));
        }
        rmax0 = fmaxf(rmax0, __shfl_xor_sync(0xffffffffu, rmax0, 1));
        rmax0 = fmaxf(rmax0, __shfl_xor_sync(0xffffffffu, rmax0, 2));
        rmax1 = fmaxf(rmax1, __shfl_xor_sync(0xffffffffu, rmax1, 1));
        rmax1 = fmaxf(rmax1, __shfl_xor_sync(0xffffffffu, rmax1, 2));
        const float mnew0 = fmaxf(mrow0, rmax0);
        const float mnew1 = fmaxf(mrow1, rmax1);
        const float corr0 = __expf(mrow0 - mnew0);
        const float corr1 = __expf(mrow1 - mnew1);
        float ps0 = 0.f, ps1 = 0.f;
        #pragma unroll
        for (int n = 0; n < 8; n++) {
            s[n][0] = __expf(s[n][0] - mnew0);
            s[n][1] = __expf(s[n][1] - mnew0);
            s[n][2] = __expf(s[n][2] - mnew1);
            s[n][3] = __expf(s[n][3] - mnew1);
            ps0 += s[n][0] + s[n][1];
            ps1 += s[n][2] + s[n][3];
        }
        ps0 += __shfl_xor_sync(0xffffffffu, ps0, 1);
        ps0 += __shfl_xor_sync(0xffffffffu, ps0, 2);
        ps1 += __shfl_xor_sync(0xffffffffu, ps1, 1);
        ps1 += __shfl_xor_sync(0xffffffffu, ps1, 2);
        lrow0 = lrow0 * corr0 + ps0; mrow0 = mnew0;
        lrow1 = lrow1 * corr1 + ps1; mrow1 = mnew1;
        #pragma unroll
        for (int n = 0; n < 8; n++) {
            o[n][0] *= corr0; o[n][1] *= corr0;
            o[n][2] *= corr1; o[n][3] *= corr1;
        }

        // --- O += P @ V : register-only P repack (acc layout == A-frag layout) ---
        #pragma unroll
        for (int j = 0; j < 4; j++) {
            const int kb = j * 16 + 2 * t4;
            uint32_t Ah[4], Al[4];
            split2(s[2 * j][0],     s[2 * j][1],     Ah[0], Al[0]);
            split2(s[2 * j][2],     s[2 * j][3],     Ah[1], Al[1]);
            split2(s[2 * j + 1][0], s[2 * j + 1][1], Ah[2], Al[2]);
            split2(s[2 * j + 1][2], s[2 * j + 1][3], Ah[3], Al[3]);
            #pragma unroll
            for (int n = 0; n < 8; n++) {
                const int roff = (8 * n + g) * KSTR + kb;
                uint32_t bh2[2] = { *(const uint32_t*)(Vhi + roff),
                                    *(const uint32_t*)(Vhi + roff + 8) };
                uint32_t bl2[2] = { *(const uint32_t*)(Vlo + roff),
                                    *(const uint32_t*)(Vlo + roff + 8) };
                mma_bf16(o[n], Ah, bh2);
                mma_bf16(o[n], Al, bh2);
                mma_bf16(o[n], Ah, bl2);
            }
        }
    }

    // --- epilogue ---
    const float inv0 = 1.f / lrow0, inv1 = 1.f / lrow1;
    float* out0 = att + (size_t)(b * SEQ + qbase + rl0) * CDIM + h * HDIM;
    float* out1 = att + (size_t)(b * SEQ + qbase + rl1) * CDIM + h * HDIM;
    #pragma unroll
    for (int n = 0; n < 8; n++) {
        const int c0 = n * 8 + 2 * t4;
        *(float2*)(out0 + c0) = make_float2(o[n][0] * inv0, o[n][1] * inv0);
        *(float2*)(out1 + c0) = make_float2(o[n][2] * inv1, o[n][3] * inv1);
    }
}

// ===========================================================================
extern "C" void kernel_launch(void* const* d_in, const int* in_sizes, int n_in,
                              void* d_out, int out_size)
{
    const float* x      = (const float*)d_in[0];
    const float* w_qkv  = (const float*)d_in[1];
    const float* w_proj = (const float*)d_in[2];
    const float* b_proj = (const float*)d_in[3];
    float* out = (float*)d_out;

    float *qkvp, *attp, *wqkvT, *wprojT;
    cudaGetSymbolAddress((void**)&qkvp, g_qkv);
    cudaGetSymbolAddress((void**)&attp, g_att);
    cudaGetSymbolAddress((void**)&wqkvT, g_wqkvT);
    cudaGetSymbolAddress((void**)&wprojT, g_wprojT);

    cudaFuncSetAttribute(gemm_mma<3 * CDIM, false>,
                         cudaFuncAttributeMaxDynamicSharedMemorySize, GEMM_SMEM);
    cudaFuncSetAttribute(gemm_mma<CDIM, true>,
                         cudaFuncAttributeMaxDynamicSharedMemorySize, GEMM_SMEM);
    cudaFuncSetAttribute(flash_bf16,
                         cudaFuncAttributeMaxDynamicSharedMemorySize, FLASH_SMEM);

    // 0) Pre-transpose + tf32-round weights
    transpose_tf32<<<dim3(3 * CDIM / 32, CDIM / 32), dim3(32, 8)>>>(w_qkv, wqkvT, CDIM, 3 * CDIM);
    transpose_tf32<<<dim3(CDIM / 32, CDIM / 32), dim3(32, 8)>>>(w_proj, wprojT, CDIM, CDIM);

    // 1) QKV projection via mma.sync tf32
    gemm_mma<3 * CDIM, false>
        <<<dim3(3 * CDIM / 128, MROWS / 128), 256, GEMM_SMEM>>>(x, wqkvT, nullptr, qkvp);

    // 2) Causal flash attention via compensated bf16 mma
    flash_bf16<<<dim3(SEQ / 64, BATCH * NHEAD), 128, FLASH_SMEM>>>(qkvp, attp);

    // 3) Output projection + bias via mma.sync tf32
    gemm_mma<CDIM, true>
        <<<dim3(CDIM / 128, MROWS / 128), 256, GEMM_SMEM>>>(attp, wprojT, b_proj, out);
}